// round 14
// baseline (speedup 1.0000x reference)
#include <cuda_runtime.h>
#include <cuda_bf16.h>
#include <mma.h>
#include <cstdint>

using namespace nvcuda;

#define T_LEN 2048
#define B_SZ  2
#define EMB   512
#define ROWS  4096       // B*T
#define HEADS 8
#define HDIM  64
#define NHASH 2
#define FULLMASK 0xffffffffu
#define FIXCAP 8192
#define TAU 1e-3f

// ---------------------------------------------------------------------------
// Scratch
// ---------------------------------------------------------------------------
__device__ float g_Q[ROWS * EMB];
__device__ float g_K[ROWS * EMB];
__device__ float g_V[ROWS * EMB];
__device__ unsigned char g_qh[NHASH * B_SZ * HEADS * T_LEN];
__device__ unsigned char g_kh[NHASH * B_SZ * HEADS * T_LEN];
__device__ float g_att[NHASH][ROWS * EMB];
__device__ int g_qstart[32][65];
__device__ int g_kstart[32][65];
__device__ unsigned short g_qlist[32 * T_LEN];
__device__ unsigned short g_klist[32 * T_LEN];
// pre-split bf16 operands: A slots 0=query,1=key,2=value (slot 0 reused for att)
__device__ __nv_bfloat16 g_Ah[3 * ROWS * EMB];
__device__ __nv_bfloat16 g_Al[3 * ROWS * EMB];
// W slots: 0=Wq, 1=Wk, 2=Wv, 3=Wo
__device__ __nv_bfloat16 g_Wh[4 * EMB * EMB];
__device__ __nv_bfloat16 g_Wl[4 * EMB * EMB];
// ambiguous-argmax fixup list
__device__ int g_nfix;
__device__ int g_fix[FIXCAP];

// ---------------------------------------------------------------------------
// f32x2 helper (exact-fp32 hash path)
// ---------------------------------------------------------------------------
__device__ __forceinline__ float2 ffma2(float2 a, float2 b, float2 c)
{
    unsigned long long ua = *reinterpret_cast<unsigned long long*>(&a);
    unsigned long long ub = *reinterpret_cast<unsigned long long*>(&b);
    unsigned long long uc = *reinterpret_cast<unsigned long long*>(&c);
    unsigned long long ud;
    asm("fma.rn.f32x2 %0, %1, %2, %3;" : "=l"(ud) : "l"(ua), "l"(ub), "l"(uc));
    return *reinterpret_cast<float2*>(&ud);
}

// ---------------------------------------------------------------------------
// Split kernels: fp32 -> (hi, lo) bf16 pairs.
// ---------------------------------------------------------------------------
__device__ __forceinline__ void split_store4(__nv_bfloat16* dh, __nv_bfloat16* dl,
                                             float4 v)
{
    float h0 = __bfloat162float(__float2bfloat16(v.x));
    float h1 = __bfloat162float(__float2bfloat16(v.y));
    float h2 = __bfloat162float(__float2bfloat16(v.z));
    float h3 = __bfloat162float(__float2bfloat16(v.w));
    __nv_bfloat162 a, b;
    a.x = __float2bfloat16(v.x); a.y = __float2bfloat16(v.y);
    b.x = __float2bfloat16(v.z); b.y = __float2bfloat16(v.w);
    *reinterpret_cast<__nv_bfloat162*>(dh)     = a;
    *reinterpret_cast<__nv_bfloat162*>(dh + 2) = b;
    __nv_bfloat162 c, d;
    c.x = __float2bfloat16(v.x - h0); c.y = __float2bfloat16(v.y - h1);
    d.x = __float2bfloat16(v.z - h2); d.y = __float2bfloat16(v.w - h3);
    *reinterpret_cast<__nv_bfloat162*>(dl)     = c;
    *reinterpret_cast<__nv_bfloat162*>(dl + 2) = d;
}

// query/key/value inputs with QKV row remap -> g_Ah/g_Al slots 0/1/2.
// Also zeroes the fixup counter (first kernel in the launch sequence).
__global__ __launch_bounds__(256) void split_x_kernel(const float* __restrict__ query,
                                                      const float* __restrict__ key,
                                                      const float* __restrict__ value)
{
    const int t = blockIdx.y;
    if (blockIdx.x == 0 && t == 0 && threadIdx.x == 0) g_nfix = 0;
    int idx = blockIdx.x * 256 + threadIdx.x;
    int f = idx >> 7;
    int c = (idx & 127) * 4;
    int srcr = (f & 1) * T_LEN + (f >> 1);
    const float* X = (t == 0) ? query : (t == 1) ? key : value;
    float4 v = *reinterpret_cast<const float4*>(X + (size_t)srcr * EMB + c);
    size_t o = (size_t)t * ROWS * EMB + (size_t)f * EMB + c;
    split_store4(g_Ah + o, g_Al + o, v);
}

// weights Wq/Wk/Wv/Wo -> slots 0..3
__global__ __launch_bounds__(256) void split_w_kernel(const float* __restrict__ Wq,
                                                      const float* __restrict__ Wk,
                                                      const float* __restrict__ Wv,
                                                      const float* __restrict__ Wo)
{
    const int wsel = blockIdx.y;
    int idx = blockIdx.x * 256 + threadIdx.x;
    int rr = idx >> 7;
    int c = (idx & 127) * 4;
    const float* W = (wsel == 0) ? Wq : (wsel == 1) ? Wk : (wsel == 2) ? Wv : Wo;
    float4 v = *reinterpret_cast<const float4*>(W + (size_t)rr * EMB + c);
    size_t o = (size_t)wsel * EMB * EMB + (size_t)rr * EMB + c;
    split_store4(g_Wh + o, g_Wl + o, v);
}

// hash-average of g_att -> slot 0
__global__ __launch_bounds__(256) void split_att_kernel()
{
    int idx = blockIdx.x * 256 + threadIdx.x;
    int f = idx >> 7;
    int c = (idx & 127) * 4;
    size_t o = (size_t)f * EMB + c;
    float4 x = *reinterpret_cast<const float4*>(&g_att[0][o]);
    float4 y = *reinterpret_cast<const float4*>(&g_att[1][o]);
    x.x = 0.5f * (x.x + y.x); x.y = 0.5f * (x.y + y.y);
    x.z = 0.5f * (x.z + y.z); x.w = 0.5f * (x.w + y.w);
    split_store4(g_Ah + o, g_Al + o, x);
}

// ---------------------------------------------------------------------------
// TC GEMM core (proven 301.5-version mainloop), parameterized by buffers.
// ---------------------------------------------------------------------------
#define TCS2 72
#define OBS  72
#define TC_SMEM2 (4 * 128 * TCS2 * 2)    // 73728 B

// Q/K/V projections: grid (4, 32, 3); z selects A slot, W slot, bias, dst.
__global__ __launch_bounds__(256) void gemm_tc_qkv(const float* __restrict__ bq,
                                                   const float* __restrict__ bk,
                                                   const float* __restrict__ bv)
{
    extern __shared__ char raw[];
    __nv_bfloat16* Ah = reinterpret_cast<__nv_bfloat16*>(raw);
    __nv_bfloat16* Al = Ah + 128 * TCS2;
    __nv_bfloat16* Bh = Al + 128 * TCS2;
    __nv_bfloat16* Bl = Bh + 128 * TCS2;
    float* obuf = reinterpret_cast<float*>(raw);

    const int tid = threadIdx.x;
    const int bn = blockIdx.x;
    const int bm = blockIdx.y;
    const int z  = blockIdx.z;
    const int w  = tid >> 5;
    const int wm = w & 3;
    const int wn = w >> 2;

    const __nv_bfloat16* GAh = g_Ah + (size_t)z * ROWS * EMB;
    const __nv_bfloat16* GAl = g_Al + (size_t)z * ROWS * EMB;
    const __nv_bfloat16* GWh = g_Wh + (size_t)z * EMB * EMB;
    const __nv_bfloat16* GWl = g_Wl + (size_t)z * EMB * EMB;
    const float* bias = (z == 0) ? bq : (z == 1) ? bk : bv;

    wmma::fragment<wmma::accumulator, 16, 16, 16, float> acc[2][4];
#pragma unroll
    for (int im = 0; im < 2; im++)
#pragma unroll
        for (int jn = 0; jn < 4; jn++) wmma::fill_fragment(acc[im][jn], 0.f);

    for (int ks = 0; ks < EMB; ks += 64) {
        __syncthreads();
#pragma unroll
        for (int i = 0; i < 4; i++) {
            int idx = tid + i * 256;
            int row = idx >> 3;
            int seg = idx & 7;
            size_t ga = (size_t)(bm * 128 + row) * EMB + ks + seg * 8;
            size_t gb = (size_t)(bn * 128 + row) * EMB + ks + seg * 8;
            int so = row * TCS2 + seg * 8;
            *reinterpret_cast<uint4*>(Ah + so) = *reinterpret_cast<const uint4*>(GAh + ga);
            *reinterpret_cast<uint4*>(Al + so) = *reinterpret_cast<const uint4*>(GAl + ga);
            *reinterpret_cast<uint4*>(Bh + so) = *reinterpret_cast<const uint4*>(GWh + gb);
            *reinterpret_cast<uint4*>(Bl + so) = *reinterpret_cast<const uint4*>(GWl + gb);
        }
        __syncthreads();

#pragma unroll
        for (int kk = 0; kk < 4; kk++) {
            wmma::fragment<wmma::matrix_a, 16, 16, 16, __nv_bfloat16, wmma::row_major> ah[2], al[2];
#pragma unroll
            for (int im = 0; im < 2; im++) {
                wmma::load_matrix_sync(ah[im], Ah + (wm * 32 + im * 16) * TCS2 + kk * 16, TCS2);
                wmma::load_matrix_sync(al[im], Al + (wm * 32 + im * 16) * TCS2 + kk * 16, TCS2);
            }
#pragma unroll
            for (int jn = 0; jn < 4; jn++) {
                wmma::fragment<wmma::matrix_b, 16, 16, 16, __nv_bfloat16, wmma::col_major> bh, bl;
                wmma::load_matrix_sync(bh, Bh + (wn * 64 + jn * 16) * TCS2 + kk * 16, TCS2);
                wmma::load_matrix_sync(bl, Bl + (wn * 64 + jn * 16) * TCS2 + kk * 16, TCS2);
#pragma unroll
                for (int im = 0; im < 2; im++) {
                    wmma::mma_sync(acc[im][jn], ah[im], bh, acc[im][jn]);
                    wmma::mma_sync(acc[im][jn], ah[im], bl, acc[im][jn]);
                    wmma::mma_sync(acc[im][jn], al[im], bh, acc[im][jn]);
                }
            }
        }
    }

    float* dstp = (z == 0) ? g_Q : (z == 1) ? g_K : g_V;

#pragma unroll
    for (int half = 0; half < 2; half++) {
        __syncthreads();
        if (wn == half) {
#pragma unroll
            for (int im = 0; im < 2; im++)
#pragma unroll
                for (int jn = 0; jn < 4; jn++)
                    wmma::store_matrix_sync(obuf + (wm * 32 + im * 16) * OBS + jn * 16,
                                            acc[im][jn], OBS, wmma::mem_row_major);
        }
        __syncthreads();
#pragma unroll
        for (int it = 0; it < 8; it++) {
            int idx = tid + it * 256;
            int row = idx >> 4;
            int c4  = idx & 15;
            float4 v = *reinterpret_cast<const float4*>(&obuf[row * OBS + c4 * 4]);
            int colg = bn * 128 + half * 64 + c4 * 4;
            v.x += bias[colg + 0]; v.y += bias[colg + 1];
            v.z += bias[colg + 2]; v.w += bias[colg + 3];
            int ro = bm * 128 + row;
            *reinterpret_cast<float4*>(dstp + (size_t)ro * EMB + colg) = v;
        }
    }
}

// Output projection: A slot 0 (att-average), W slot 3 (Wo), transpose store.
__global__ __launch_bounds__(256) void gemm_tc_out(float* __restrict__ out,
                                                   const float* __restrict__ bias)
{
    extern __shared__ char raw[];
    __nv_bfloat16* Ah = reinterpret_cast<__nv_bfloat16*>(raw);
    __nv_bfloat16* Al = Ah + 128 * TCS2;
    __nv_bfloat16* Bh = Al + 128 * TCS2;
    __nv_bfloat16* Bl = Bh + 128 * TCS2;
    float* obuf = reinterpret_cast<float*>(raw);

    const int tid = threadIdx.x;
    const int bn = blockIdx.x;
    const int bm = blockIdx.y;
    const int w  = tid >> 5;
    const int wm = w & 3;
    const int wn = w >> 2;

    const __nv_bfloat16* GWh = g_Wh + (size_t)3 * EMB * EMB;
    const __nv_bfloat16* GWl = g_Wl + (size_t)3 * EMB * EMB;

    wmma::fragment<wmma::accumulator, 16, 16, 16, float> acc[2][4];
#pragma unroll
    for (int im = 0; im < 2; im++)
#pragma unroll
        for (int jn = 0; jn < 4; jn++) wmma::fill_fragment(acc[im][jn], 0.f);

    for (int ks = 0; ks < EMB; ks += 64) {
        __syncthreads();
#pragma unroll
        for (int i = 0; i < 4; i++) {
            int idx = tid + i * 256;
            int row = idx >> 3;
            int seg = idx & 7;
            size_t ga = (size_t)(bm * 128 + row) * EMB + ks + seg * 8;
            size_t gb = (size_t)(bn * 128 + row) * EMB + ks + seg * 8;
            int so = row * TCS2 + seg * 8;
            *reinterpret_cast<uint4*>(Ah + so) = *reinterpret_cast<const uint4*>(g_Ah + ga);
            *reinterpret_cast<uint4*>(Al + so) = *reinterpret_cast<const uint4*>(g_Al + ga);
            *reinterpret_cast<uint4*>(Bh + so) = *reinterpret_cast<const uint4*>(GWh + gb);
            *reinterpret_cast<uint4*>(Bl + so) = *reinterpret_cast<const uint4*>(GWl + gb);
        }
        __syncthreads();

#pragma unroll
        for (int kk = 0; kk < 4; kk++) {
            wmma::fragment<wmma::matrix_a, 16, 16, 16, __nv_bfloat16, wmma::row_major> ah[2], al[2];
#pragma unroll
            for (int im = 0; im < 2; im++) {
                wmma::load_matrix_sync(ah[im], Ah + (wm * 32 + im * 16) * TCS2 + kk * 16, TCS2);
                wmma::load_matrix_sync(al[im], Al + (wm * 32 + im * 16) * TCS2 + kk * 16, TCS2);
            }
#pragma unroll
            for (int jn = 0; jn < 4; jn++) {
                wmma::fragment<wmma::matrix_b, 16, 16, 16, __nv_bfloat16, wmma::col_major> bh, bl;
                wmma::load_matrix_sync(bh, Bh + (wn * 64 + jn * 16) * TCS2 + kk * 16, TCS2);
                wmma::load_matrix_sync(bl, Bl + (wn * 64 + jn * 16) * TCS2 + kk * 16, TCS2);
#pragma unroll
                for (int im = 0; im < 2; im++) {
                    wmma::mma_sync(acc[im][jn], ah[im], bh, acc[im][jn]);
                    wmma::mma_sync(acc[im][jn], ah[im], bl, acc[im][jn]);
                    wmma::mma_sync(acc[im][jn], al[im], bh, acc[im][jn]);
                }
            }
        }
    }

#pragma unroll
    for (int half = 0; half < 2; half++) {
        __syncthreads();
        if (wn == half) {
#pragma unroll
            for (int im = 0; im < 2; im++)
#pragma unroll
                for (int jn = 0; jn < 4; jn++)
                    wmma::store_matrix_sync(obuf + (wm * 32 + im * 16) * OBS + jn * 16,
                                            acc[im][jn], OBS, wmma::mem_row_major);
        }
        __syncthreads();
#pragma unroll
        for (int it = 0; it < 8; it++) {
            int idx = tid + it * 256;
            int row = idx >> 4;
            int c4  = idx & 15;
            float4 v = *reinterpret_cast<const float4*>(&obuf[row * OBS + c4 * 4]);
            int colg = bn * 128 + half * 64 + c4 * 4;
            v.x += bias[colg + 0]; v.y += bias[colg + 1];
            v.z += bias[colg + 2]; v.w += bias[colg + 3];
            int ro = bm * 128 + row;
            int g = (ro & 2047) * B_SZ + (ro >> 11);
            *reinterpret_cast<float4*>(out + (size_t)g * EMB + colg) = v;
        }
    }
}

// ---------------------------------------------------------------------------
// Kernel 2: LSH hashing GEMM (64x128 tile) + guarded argmax.
// Tracks top-2; rows with gap < TAU are appended to the fixup list.
// ---------------------------------------------------------------------------
__global__ __launch_bounds__(256) void hash_gemm(const float* __restrict__ lshW,
                                                 const float* __restrict__ lshb)
{
    __shared__ float As2h[2][16][130];
    __shared__ float Bsh[2][16][132];
    const int tid = threadIdx.x;
    const int bm = blockIdx.x;
    const int tensor = blockIdx.y;
    const int tx = tid & 15, ty = tid >> 4;

    const float* A = tensor ? g_K : g_Q;
    unsigned char* dst = tensor ? g_kh : g_qh;

    const int arr = tid >> 2, ak4 = tid & 3;
    const int br0 = (tid * 2) >> 2, bk40 = (tid * 2) & 3;
    const int br1 = (tid * 2 + 1) >> 2, bk41 = (tid * 2 + 1) & 3;
    const float* Abase = A + (size_t)(bm * 64 + arr) * 64 + ak4 * 4;
    const float* B0 = lshW + (size_t)br0 * 64 + bk40 * 4;
    const float* B1 = lshW + (size_t)br1 * 64 + bk41 * 4;

    float2 acc[4][4];
#pragma unroll
    for (int i = 0; i < 4; i++)
#pragma unroll
        for (int p = 0; p < 4; p++) acc[i][p] = make_float2(0.f, 0.f);

    float4 ra = *reinterpret_cast<const float4*>(Abase);
    float4 rb0 = *reinterpret_cast<const float4*>(B0);
    float4 rb1 = *reinterpret_cast<const float4*>(B1);
    {
        float va[4] = {ra.x, ra.y, ra.z, ra.w};
#pragma unroll
        for (int c = 0; c < 4; c++) {
            As2h[0][ak4 * 4 + c][2 * arr] = va[c];
            As2h[0][ak4 * 4 + c][2 * arr + 1] = va[c];
        }
        Bsh[0][bk40 * 4 + 0][br0] = rb0.x; Bsh[0][bk40 * 4 + 1][br0] = rb0.y;
        Bsh[0][bk40 * 4 + 2][br0] = rb0.z; Bsh[0][bk40 * 4 + 3][br0] = rb0.w;
        Bsh[0][bk41 * 4 + 0][br1] = rb1.x; Bsh[0][bk41 * 4 + 1][br1] = rb1.y;
        Bsh[0][bk41 * 4 + 2][br1] = rb1.z; Bsh[0][bk41 * 4 + 3][br1] = rb1.w;
    }
    __syncthreads();

    for (int s = 0; s < 4; s++) {
        const int cur = s & 1;
        if (s + 1 < 4) {
            ra  = *reinterpret_cast<const float4*>(Abase + (s + 1) * 16);
            rb0 = *reinterpret_cast<const float4*>(B0 + (s + 1) * 16);
            rb1 = *reinterpret_cast<const float4*>(B1 + (s + 1) * 16);
        }
#pragma unroll
        for (int k = 0; k < 16; k++) {
            float2 avd[4], bv2[4];
#pragma unroll
            for (int i = 0; i < 4; i++)
                avd[i] = *reinterpret_cast<const float2*>(&As2h[cur][k][2 * (ty * 4 + i)]);
#pragma unroll
            for (int p = 0; p < 4; p++)
                bv2[p] = *reinterpret_cast<const float2*>(&Bsh[cur][k][p * 32 + tx * 2]);
#pragma unroll
            for (int i = 0; i < 4; i++)
#pragma unroll
                for (int p = 0; p < 4; p++)
                    acc[i][p] = ffma2(avd[i], bv2[p], acc[i][p]);
        }
        if (s + 1 < 4) {
            __syncthreads();
            const int nxt = cur ^ 1;
            float va[4] = {ra.x, ra.y, ra.z, ra.w};
#pragma unroll
            for (int c = 0; c < 4; c++) {
                As2h[nxt][ak4 * 4 + c][2 * arr] = va[c];
                As2h[nxt][ak4 * 4 + c][2 * arr + 1] = va[c];
            }
            Bsh[nxt][bk40 * 4 + 0][br0] = rb0.x; Bsh[nxt][bk40 * 4 + 1][br0] = rb0.y;
            Bsh[nxt][bk40 * 4 + 2][br0] = rb0.z; Bsh[nxt][bk40 * 4 + 3][br0] = rb0.w;
            Bsh[nxt][bk41 * 4 + 0][br1] = rb1.x; Bsh[nxt][bk41 * 4 + 1][br1] = rb1.y;
            Bsh[nxt][bk41 * 4 + 2][br1] = rb1.z; Bsh[nxt][bk41 * 4 + 3][br1] = rb1.w;
            __syncthreads();
        }
    }

    float2 bb2[4];
#pragma unroll
    for (int p = 0; p < 4; p++)
        bb2[p] = *reinterpret_cast<const float2*>(lshb + p * 32 + tx * 2);

#pragma unroll
    for (int i = 0; i < 4; i++) {
        const int m  = bm * 64 + ty * 4 + i;
        const int r  = m >> 3, h = m & 7;
        const int nb = r >> 11, nt = r & 2047;
#pragma unroll
        for (int hh = 0; hh < 2; hh++) {
            float2 c0 = acc[i][2 * hh];
            float2 c1 = acc[i][2 * hh + 1];
            c0.x += bb2[2 * hh].x;     c0.y += bb2[2 * hh].y;
            c1.x += bb2[2 * hh + 1].x; c1.y += bb2[2 * hh + 1].y;
            // lane-local top-2 over 4 candidates (index-ascending, strict >)
            float bvv = c0.x; int bi = tx * 2; float sec = -INFINITY;
            if (c0.y > bvv) { sec = bvv; bvv = c0.y; bi = tx * 2 + 1; }
            else sec = fmaxf(sec, c0.y);
            if (c1.x > bvv) { sec = bvv; bvv = c1.x; bi = 32 + tx * 2; }
            else sec = fmaxf(sec, c1.x);
            if (c1.y > bvv) { sec = bvv; bvv = c1.y; bi = 33 + tx * 2; }
            else sec = fmaxf(sec, c1.y);
#pragma unroll
            for (int off = 1; off < 16; off <<= 1) {
                float ov = __shfl_xor_sync(FULLMASK, bvv, off);
                int   oi = __shfl_xor_sync(FULLMASK, bi, off);
                float os = __shfl_xor_sync(FULLMASK, sec, off);
                if (ov > bvv || (ov == bvv && oi < bi)) {
                    sec = fmaxf(fmaxf(sec, os), bvv);
                    bvv = ov; bi = oi;
                } else {
                    sec = fmaxf(fmaxf(sec, os), ov);
                }
            }
            if (tx == 0) {
                dst[((hh * B_SZ + nb) * HEADS + h) * T_LEN + nt] = (unsigned char)bi;
                if (bvv - sec < TAU) {
                    int ix = atomicAdd(&g_nfix, 1);
                    if (ix < FIXCAP)
                        g_fix[ix] = m | (hh << 15) | (tensor << 16);
                }
            }
        }
    }
}

// ---------------------------------------------------------------------------
// Fixup: exact-fp32 recompute of flagged (row, head, hash) argmaxes.
// One warp per entry.
// ---------------------------------------------------------------------------
__global__ __launch_bounds__(256) void hash_fixup(
    const float* __restrict__ query, const float* __restrict__ key,
    const float* __restrict__ Wq, const float* __restrict__ Wk,
    const float* __restrict__ bq, const float* __restrict__ bk,
    const float* __restrict__ lshW, const float* __restrict__ lshb)
{
    __shared__ float qsm[8][64];
    const int lw = threadIdx.x >> 5;
    const int lane = threadIdx.x & 31;
    const int wid = blockIdx.x * 8 + lw;
    const int nw = gridDim.x * 8;
    const int n = min(g_nfix, FIXCAP);

    for (int e = wid; e < n; e += nw) {
        int ent = g_fix[e];
        int m = ent & 0x7FFF;
        int hh = (ent >> 15) & 1;
        int tensor = (ent >> 16) & 1;
        int r = m >> 3, h = m & 7;
        const float* X = tensor ? key : query;
        const float* W = tensor ? Wk : Wq;
        const float* bias = tensor ? bk : bq;
        unsigned char* dst = tensor ? g_kh : g_qh;
        int srcr = (r & 1) * T_LEN + (r >> 1);
        const float* xrow = X + (size_t)srcr * EMB;
        // exact q head-slice: dims lane, lane+32
#pragma unroll
        for (int dd = 0; dd < 2; dd++) {
            int d = lane + dd * 32;
            const float* wrow = W + (size_t)(h * 64 + d) * EMB;
            float a = bias[h * 64 + d];
            for (int e2 = 0; e2 < EMB; e2++) a += xrow[e2] * wrow[e2];
            qsm[lw][d] = a;
        }
        __syncwarp();
        // exact hash scores + argmax (ties -> lowest index)
        float s0, s1;
        {
            const float* hw0 = lshW + ((size_t)hh * 64 + lane) * 64;
            const float* hw1 = lshW + ((size_t)hh * 64 + lane + 32) * 64;
            s0 = lshb[hh * 64 + lane];
            s1 = lshb[hh * 64 + lane + 32];
            for (int d2 = 0; d2 < 64; d2++) {
                float qv = qsm[lw][d2];
                s0 += qv * hw0[d2];
                s1 += qv * hw1[d2];
            }
        }
        float bvv = s0; int bd = lane;
        if (s1 > bvv) { bvv = s1; bd = lane + 32; }
#pragma unroll
        for (int off = 16; off; off >>= 1) {
            float ov = __shfl_xor_sync(FULLMASK, bvv, off);
            int   od = __shfl_xor_sync(FULLMASK, bd, off);
            if (ov > bvv || (ov == bvv && od < bd)) { bvv = ov; bd = od; }
        }
        if (lane == 0) {
            int nb = r >> 11, nt = r & 2047;
            dst[((hh * B_SZ + nb) * HEADS + h) * T_LEN + nt] = (unsigned char)bd;
        }
        __syncwarp();
    }
}

// ---------------------------------------------------------------------------
// Kernel 3: bucketize — grid (32 combos, 2 tensors)
// ---------------------------------------------------------------------------
__global__ __launch_bounds__(256) void bucketize_kernel()
{
    __shared__ int cnt[64];
    __shared__ int off[64];
    const int combo = blockIdx.x;
    const int tensor = blockIdx.y;
    const int tid = threadIdx.x;

    const unsigned char* hsrc = (tensor ? g_kh : g_qh) + combo * T_LEN;
    int* startp = tensor ? g_kstart[combo] : g_qstart[combo];
    unsigned short* listp = (tensor ? g_klist : g_qlist) + combo * T_LEN;

    if (tid < 64) cnt[tid] = 0;
    __syncthreads();

    for (int i = tid; i < T_LEN; i += 256)
        atomicAdd(&cnt[hsrc[i]], 1);
    __syncthreads();

    if (tid == 0) {
        int s = 0;
        for (int j = 0; j < 64; j++) { startp[j] = s; off[j] = s; s += cnt[j]; }
        startp[64] = s;
    }
    __syncthreads();

    for (int i = tid; i < T_LEN; i += 256) {
        int p = atomicAdd(&off[hsrc[i]], 1);
        listp[p] = (unsigned short)i;
    }
}

// ---------------------------------------------------------------------------
// Kernel 4: per-bucket flash attention, 32x32 tiles.
// ---------------------------------------------------------------------------
#define QS  68
#define KSK 34
#define KSP 33

__global__ __launch_bounds__(256) void attn_bucket_kernel()
{
    __shared__ float qsh[32 * QS];
    __shared__ float ksh[64 * KSK];
    __shared__ float vsh[32 * QS];
    __shared__ float psh[32 * KSP];
    __shared__ int   qid[32];

    const int bucket = blockIdx.x;
    const int combo  = blockIdx.y;
    const int hash = combo >> 4;
    const int b    = (combo >> 3) & 1;
    const int h    = combo & 7;
    const int tid  = threadIdx.x;
    const int tx = tid & 15, ty = tid >> 4;

    const int qs = g_qstart[combo][bucket];
    const int nq = g_qstart[combo][bucket + 1] - qs;
    if (nq == 0) return;
    const int ks = g_kstart[combo][bucket];
    const int kn = g_kstart[combo][bucket + 1] - ks;

    const unsigned short* qlist = g_qlist + combo * T_LEN;
    const unsigned short* klist = g_klist + combo * T_LEN;

    float* Op = g_att[hash] + (size_t)b * T_LEN * EMB + h * HDIM;

    if (bucket >= 32 || kn == 0) {
        for (int idx = tid; idx < nq * 16; idx += 256) {
            int qi = idx >> 4, sl = idx & 15;
            int t = qlist[qs + qi];
            *reinterpret_cast<float4*>(Op + (size_t)t * EMB + sl * 4) =
                make_float4(0.f, 0.f, 0.f, 0.f);
        }
        return;
    }

    const float* Qp = g_Q + (size_t)b * T_LEN * EMB + h * HDIM;
    const float* Kp = g_K + (size_t)b * T_LEN * EMB + h * HDIM;
    const float* Vp = g_V + (size_t)b * T_LEN * EMB + h * HDIM;

    for (int q0 = 0; q0 < nq; q0 += 32) {
        const int cq = min(32, nq - q0);
        __syncthreads();
        for (int task = tid; task < 512; task += 256) {
            int row = task >> 4, slot = task & 15;
            if (row < cq) {
                int t = qlist[qs + q0 + row];
                if (slot == 0) qid[row] = t;
                float4 v4 = *reinterpret_cast<const float4*>(Qp + (size_t)t * EMB + slot * 4);
                float* d = &qsh[row * QS + slot * 4];
                d[0] = v4.x; d[1] = v4.y; d[2] = v4.z; d[3] = v4.w;
            }
        }
        __syncthreads();

        float m[2], l[2], o[2][4];
#pragma unroll
        for (int i = 0; i < 2; i++) {
            m[i] = -INFINITY; l[i] = 0.f;
#pragma unroll
            for (int d = 0; d < 4; d++) o[i][d] = 0.f;
        }

        for (int k0 = 0; k0 < kn; k0 += 32) {
            const int cnk = min(32, kn - k0);
            __syncthreads();
            for (int task = tid; task < 512; task += 256) {
                int row = task >> 4, slot = task & 15;
                float* dv = &vsh[row * QS + slot * 4];
                if (row < cnk) {
                    int t = klist[ks + k0 + row];
                    float4 k4 = *reinterpret_cast<const float4*>(Kp + (size_t)t * EMB + slot * 4);
                    ksh[(slot * 4 + 0) * KSK + row] = k4.x;
                    ksh[(slot * 4 + 1) * KSK + row] = k4.y;
                    ksh[(slot * 4 + 2) * KSK + row] = k4.z;
                    ksh[(slot * 4 + 3) * KSK + row] = k4.w;
                    float4 v4 = *reinterpret_cast<const float4*>(Vp + (size_t)t * EMB + slot * 4);
                    dv[0] = v4.x; dv[1] = v4.y; dv[2] = v4.z; dv[3] = v4.w;
                } else {
                    dv[0] = 0.f; dv[1] = 0.f; dv[2] = 0.f; dv[3] = 0.f;
                }
            }
            __syncthreads();

            float s00 = 0.f, s01 = 0.f, s10 = 0.f, s11 = 0.f;
            const float* q0p = &qsh[(ty * 2 + 0) * QS];
            const float* q1p = &qsh[(ty * 2 + 1) * QS];
#pragma unroll 8
            for (int k = 0; k < 64; k += 2) {
                float2 a0 = *reinterpret_cast<const float2*>(&q0p[k]);
                float2 a1 = *reinterpret_cast<const float2*>(&q1p[k]);
                float2 b0 = *reinterpret_cast<const float2*>(&ksh[k * KSK + tx * 2]);
                float2 b1 = *reinterpret_cast<const float2*>(&ksh[(k + 1) * KSK + tx * 2]);
                s00 += a0.x * b0.x + a0.y * b1.x;
                s01 += a0.x * b0.y + a0.y * b1.y;
                s10 += a1.x * b0.x + a1.y * b1.x;
                s11 += a1.x * b0.y + a1.y * b1.y;
            }
            const bool c0 = (tx * 2 + 0) < cnk;
            const bool c1 = (tx * 2 + 1) < cnk;
            float s4[2][2];
            s4[0][0] = c0 ? s00 * 0.125f : -INFINITY;
            s4[0][1] = c1 ? s01 * 0.125f : -INFINITY;
            s4[1][0] = c0 ? s10 * 0.125f : -INFINITY;
            s4[1][1] = c1 ? s11 * 0.125f : -INFINITY;

#pragma unroll
            for (int i = 0; i < 2; i++) {
                float cm = fmaxf(s4[i][0], s4[i][1]);
#pragma unroll
                for (int off = 1; off < 16; off <<= 1)
                    cm = fmaxf(cm, __shfl_xor_sync(FULLMASK, cm, off));
                float mn = fmaxf(m[i], cm);
                float corr = __expf(m[i] - mn);
                m[i] = mn;
                float w0 = __expf(s4[i][0] - mn);
                float w1 = __expf(s4[i][1] - mn);
                s4[i][0] = w0; s4[i][1] = w1;
                float ps = w0 + w1;
#pragma unroll
                for (int off = 1; off < 16; off <<= 1)
                    ps += __shfl_xor_sync(FULLMASK, ps, off);
                l[i] = l[i] * corr + ps;
#pragma unroll
                for (int d = 0; d < 4; d++) o[i][d] *= corr;
            }
#pragma unroll
            for (int i = 0; i < 2; i++) {
                psh[(ty * 2 + i) * KSP + tx * 2 + 0] = s4[i][0];
                psh[(ty * 2 + i) * KSP + tx * 2 + 1] = s4[i][1];
            }
            __syncthreads();
            const float* p0 = &psh[(ty * 2 + 0) * KSP];
            const float* p1 = &psh[(ty * 2 + 1) * KSP];
#pragma unroll 8
            for (int j = 0; j < 32; j++) {
                float pv0 = p0[j];
                float pv1 = p1[j];
                float4 vv = *reinterpret_cast<const float4*>(&vsh[j * QS + tx * 4]);
                o[0][0] += pv0 * vv.x; o[0][1] += pv0 * vv.y;
                o[0][2] += pv0 * vv.z; o[0][3] += pv0 * vv.w;
                o[1][0] += pv1 * vv.x; o[1][1] += pv1 * vv.y;
                o[1][2] += pv1 * vv.z; o[1][3] += pv1 * vv.w;
            }
        }

#pragma unroll
        for (int i = 0; i < 2; i++) {
            int row = ty * 2 + i;
            if (row < cq) {
                float inv = 1.f / l[i];
                int t = qid[row];
                float4 v;
                v.x = o[i][0] * inv; v.y = o[i][1] * inv;
                v.z = o[i][2] * inv; v.w = o[i][3] * inv;
                *reinterpret_cast<float4*>(Op + (size_t)t * EMB + tx * 4) = v;
            }
        }
    }
}

// ---------------------------------------------------------------------------
extern "C" void kernel_launch(void* const* d_in, const int* in_sizes, int n_in,
                              void* d_out, int out_size)
{
    (void)in_sizes; (void)n_in; (void)out_size;
    const float* query = (const float*)d_in[0];
    const float* key   = (const float*)d_in[1];
    const float* value = (const float*)d_in[2];
    const float* Wq = (const float*)d_in[3];
    const float* bq = (const float*)d_in[4];
    const float* Wk = (const float*)d_in[5];
    const float* bk = (const float*)d_in[6];
    const float* Wv = (const float*)d_in[7];
    const float* bv = (const float*)d_in[8];
    const float* Wo = (const float*)d_in[9];
    const float* bo = (const float*)d_in[10];
    const float* lshW = (const float*)d_in[11];
    const float* lshb = (const float*)d_in[12];
    float* out = (float*)d_out;

    cudaFuncSetAttribute(gemm_tc_qkv, cudaFuncAttributeMaxDynamicSharedMemorySize, TC_SMEM2);
    cudaFuncSetAttribute(gemm_tc_out, cudaFuncAttributeMaxDynamicSharedMemorySize, TC_SMEM2);

    split_x_kernel<<<dim3(ROWS * 128 / 256, 3), 256>>>(query, key, value);
    split_w_kernel<<<dim3(EMB * 128 / 256, 4), 256>>>(Wq, Wk, Wv, Wo);

    gemm_tc_qkv<<<dim3(EMB / 128, ROWS / 128, 3), 256, TC_SMEM2>>>(bq, bk, bv);
    hash_gemm<<<dim3(512, 2), 256>>>(lshW, lshb);
    hash_fixup<<<64, 256>>>(query, key, Wq, Wk, bq, bk, lshW, lshb);
    bucketize_kernel<<<dim3(32, 2), 256>>>();
    attn_bucket_kernel<<<dim3(64, 32), 256>>>();

    split_att_kernel<<<ROWS * 128 / 256, 256>>>();
    gemm_tc_out<<<dim3(EMB / 128, ROWS / 128), 256, TC_SMEM2>>>(out, bo);
}

// round 15
// speedup vs baseline: 1.3981x; 1.3981x over previous
#include <cuda_runtime.h>
#include <cuda_bf16.h>
#include <mma.h>
#include <cstdint>

using namespace nvcuda;

#define T_LEN 2048
#define B_SZ  2
#define EMB   512
#define ROWS  4096       // B*T
#define HEADS 8
#define HDIM  64
#define NHASH 2
#define FULLMASK 0xffffffffu
#define FIXCAP 8192
#define TAU 1e-3f

// ---------------------------------------------------------------------------
// Scratch
// ---------------------------------------------------------------------------
__device__ float g_Q[ROWS * EMB];
__device__ float g_K[ROWS * EMB];
__device__ float g_V[ROWS * EMB];
__device__ unsigned char g_qh[NHASH * B_SZ * HEADS * T_LEN];
__device__ unsigned char g_kh[NHASH * B_SZ * HEADS * T_LEN];
__device__ float g_att[NHASH][ROWS * EMB];
__device__ int g_qstart[32][65];
__device__ int g_kstart[32][65];
__device__ unsigned short g_qlist[32 * T_LEN];
__device__ unsigned short g_klist[32 * T_LEN];
// pre-split bf16 operands: A slots 0=query,1=key,2=value (slot 0 reused for att)
__device__ __nv_bfloat16 g_Ah[3 * ROWS * EMB];
__device__ __nv_bfloat16 g_Al[3 * ROWS * EMB];
// W slots: 0=Wq, 1=Wk, 2=Wv, 3=Wo
__device__ __nv_bfloat16 g_Wh[4 * EMB * EMB];
__device__ __nv_bfloat16 g_Wl[4 * EMB * EMB];
// ambiguous-argmax fixup list
__device__ int g_nfix;
__device__ int g_fix[FIXCAP];

// ---------------------------------------------------------------------------
// f32x2 helper (exact-fp32 hash path)
// ---------------------------------------------------------------------------
__device__ __forceinline__ float2 ffma2(float2 a, float2 b, float2 c)
{
    unsigned long long ua = *reinterpret_cast<unsigned long long*>(&a);
    unsigned long long ub = *reinterpret_cast<unsigned long long*>(&b);
    unsigned long long uc = *reinterpret_cast<unsigned long long*>(&c);
    unsigned long long ud;
    asm("fma.rn.f32x2 %0, %1, %2, %3;" : "=l"(ud) : "l"(ua), "l"(ub), "l"(uc));
    return *reinterpret_cast<float2*>(&ud);
}

// ---------------------------------------------------------------------------
// Split kernels: fp32 -> (hi, lo) bf16 pairs.
// ---------------------------------------------------------------------------
__device__ __forceinline__ void split_store4(__nv_bfloat16* dh, __nv_bfloat16* dl,
                                             float4 v)
{
    float h0 = __bfloat162float(__float2bfloat16(v.x));
    float h1 = __bfloat162float(__float2bfloat16(v.y));
    float h2 = __bfloat162float(__float2bfloat16(v.z));
    float h3 = __bfloat162float(__float2bfloat16(v.w));
    __nv_bfloat162 a, b;
    a.x = __float2bfloat16(v.x); a.y = __float2bfloat16(v.y);
    b.x = __float2bfloat16(v.z); b.y = __float2bfloat16(v.w);
    *reinterpret_cast<__nv_bfloat162*>(dh)     = a;
    *reinterpret_cast<__nv_bfloat162*>(dh + 2) = b;
    __nv_bfloat162 c, d;
    c.x = __float2bfloat16(v.x - h0); c.y = __float2bfloat16(v.y - h1);
    d.x = __float2bfloat16(v.z - h2); d.y = __float2bfloat16(v.w - h3);
    *reinterpret_cast<__nv_bfloat162*>(dl)     = c;
    *reinterpret_cast<__nv_bfloat162*>(dl + 2) = d;
}

__global__ __launch_bounds__(256) void split_x_kernel(const float* __restrict__ query,
                                                      const float* __restrict__ key,
                                                      const float* __restrict__ value)
{
    const int t = blockIdx.y;
    if (blockIdx.x == 0 && t == 0 && threadIdx.x == 0) g_nfix = 0;
    int idx = blockIdx.x * 256 + threadIdx.x;
    int f = idx >> 7;
    int c = (idx & 127) * 4;
    int srcr = (f & 1) * T_LEN + (f >> 1);
    const float* X = (t == 0) ? query : (t == 1) ? key : value;
    float4 v = *reinterpret_cast<const float4*>(X + (size_t)srcr * EMB + c);
    size_t o = (size_t)t * ROWS * EMB + (size_t)f * EMB + c;
    split_store4(g_Ah + o, g_Al + o, v);
}

__global__ __launch_bounds__(256) void split_w_kernel(const float* __restrict__ Wq,
                                                      const float* __restrict__ Wk,
                                                      const float* __restrict__ Wv,
                                                      const float* __restrict__ Wo)
{
    const int wsel = blockIdx.y;
    int idx = blockIdx.x * 256 + threadIdx.x;
    int rr = idx >> 7;
    int c = (idx & 127) * 4;
    const float* W = (wsel == 0) ? Wq : (wsel == 1) ? Wk : (wsel == 2) ? Wv : Wo;
    float4 v = *reinterpret_cast<const float4*>(W + (size_t)rr * EMB + c);
    size_t o = (size_t)wsel * EMB * EMB + (size_t)rr * EMB + c;
    split_store4(g_Wh + o, g_Wl + o, v);
}

__global__ __launch_bounds__(256) void split_att_kernel()
{
    int idx = blockIdx.x * 256 + threadIdx.x;
    int f = idx >> 7;
    int c = (idx & 127) * 4;
    size_t o = (size_t)f * EMB + c;
    float4 x = *reinterpret_cast<const float4*>(&g_att[0][o]);
    float4 y = *reinterpret_cast<const float4*>(&g_att[1][o]);
    x.x = 0.5f * (x.x + y.x); x.y = 0.5f * (x.y + y.y);
    x.z = 0.5f * (x.z + y.z); x.w = 0.5f * (x.w + y.w);
    split_store4(g_Ah + o, g_Al + o, x);
}

// ---------------------------------------------------------------------------
// TC GEMM core (proven mainloop), 2-CTA/SM residency requested.
// ---------------------------------------------------------------------------
#define TCS2 72
#define OBS  72
#define TC_SMEM2 (4 * 128 * TCS2 * 2)    // 73728 B

// Q/K/V projections: grid (4, 32, 3); z selects A slot, W slot, bias, dst.
__global__ __launch_bounds__(256, 2) void gemm_tc_qkv(const float* __restrict__ bq,
                                                      const float* __restrict__ bk,
                                                      const float* __restrict__ bv)
{
    extern __shared__ char raw[];
    __nv_bfloat16* Ah = reinterpret_cast<__nv_bfloat16*>(raw);
    __nv_bfloat16* Al = Ah + 128 * TCS2;
    __nv_bfloat16* Bh = Al + 128 * TCS2;
    __nv_bfloat16* Bl = Bh + 128 * TCS2;
    float* obuf = reinterpret_cast<float*>(raw);

    const int tid = threadIdx.x;
    const int bn = blockIdx.x;
    const int bm = blockIdx.y;
    const int z  = blockIdx.z;
    const int w  = tid >> 5;
    const int wm = w & 3;
    const int wn = w >> 2;

    const __nv_bfloat16* GAh = g_Ah + (size_t)z * ROWS * EMB;
    const __nv_bfloat16* GAl = g_Al + (size_t)z * ROWS * EMB;
    const __nv_bfloat16* GWh = g_Wh + (size_t)z * EMB * EMB;
    const __nv_bfloat16* GWl = g_Wl + (size_t)z * EMB * EMB;
    const float* bias = (z == 0) ? bq : (z == 1) ? bk : bv;

    wmma::fragment<wmma::accumulator, 16, 16, 16, float> acc[2][4];
#pragma unroll
    for (int im = 0; im < 2; im++)
#pragma unroll
        for (int jn = 0; jn < 4; jn++) wmma::fill_fragment(acc[im][jn], 0.f);

    for (int ks = 0; ks < EMB; ks += 64) {
        __syncthreads();
#pragma unroll
        for (int i = 0; i < 4; i++) {
            int idx = tid + i * 256;
            int row = idx >> 3;
            int seg = idx & 7;
            size_t ga = (size_t)(bm * 128 + row) * EMB + ks + seg * 8;
            size_t gb = (size_t)(bn * 128 + row) * EMB + ks + seg * 8;
            int so = row * TCS2 + seg * 8;
            *reinterpret_cast<uint4*>(Ah + so) = *reinterpret_cast<const uint4*>(GAh + ga);
            *reinterpret_cast<uint4*>(Al + so) = *reinterpret_cast<const uint4*>(GAl + ga);
            *reinterpret_cast<uint4*>(Bh + so) = *reinterpret_cast<const uint4*>(GWh + gb);
            *reinterpret_cast<uint4*>(Bl + so) = *reinterpret_cast<const uint4*>(GWl + gb);
        }
        __syncthreads();

#pragma unroll
        for (int kk = 0; kk < 4; kk++) {
            wmma::fragment<wmma::matrix_a, 16, 16, 16, __nv_bfloat16, wmma::row_major> ah[2], al[2];
#pragma unroll
            for (int im = 0; im < 2; im++) {
                wmma::load_matrix_sync(ah[im], Ah + (wm * 32 + im * 16) * TCS2 + kk * 16, TCS2);
                wmma::load_matrix_sync(al[im], Al + (wm * 32 + im * 16) * TCS2 + kk * 16, TCS2);
            }
#pragma unroll
            for (int jn = 0; jn < 4; jn++) {
                wmma::fragment<wmma::matrix_b, 16, 16, 16, __nv_bfloat16, wmma::col_major> bh, bl;
                wmma::load_matrix_sync(bh, Bh + (wn * 64 + jn * 16) * TCS2 + kk * 16, TCS2);
                wmma::load_matrix_sync(bl, Bl + (wn * 64 + jn * 16) * TCS2 + kk * 16, TCS2);
#pragma unroll
                for (int im = 0; im < 2; im++) {
                    wmma::mma_sync(acc[im][jn], ah[im], bh, acc[im][jn]);
                    wmma::mma_sync(acc[im][jn], ah[im], bl, acc[im][jn]);
                    wmma::mma_sync(acc[im][jn], al[im], bh, acc[im][jn]);
                }
            }
        }
    }

    float* dstp = (z == 0) ? g_Q : (z == 1) ? g_K : g_V;

#pragma unroll
    for (int half = 0; half < 2; half++) {
        __syncthreads();
        if (wn == half) {
#pragma unroll
            for (int im = 0; im < 2; im++)
#pragma unroll
                for (int jn = 0; jn < 4; jn++)
                    wmma::store_matrix_sync(obuf + (wm * 32 + im * 16) * OBS + jn * 16,
                                            acc[im][jn], OBS, wmma::mem_row_major);
        }
        __syncthreads();
#pragma unroll
        for (int it = 0; it < 8; it++) {
            int idx = tid + it * 256;
            int row = idx >> 4;
            int c4  = idx & 15;
            float4 v = *reinterpret_cast<const float4*>(&obuf[row * OBS + c4 * 4]);
            int colg = bn * 128 + half * 64 + c4 * 4;
            v.x += bias[colg + 0]; v.y += bias[colg + 1];
            v.z += bias[colg + 2]; v.w += bias[colg + 3];
            int ro = bm * 128 + row;
            *reinterpret_cast<float4*>(dstp + (size_t)ro * EMB + colg) = v;
        }
    }
}

// Output projection: A slot 0 (att-average), W slot 3 (Wo), transpose store.
__global__ __launch_bounds__(256, 2) void gemm_tc_out(float* __restrict__ out,
                                                      const float* __restrict__ bias)
{
    extern __shared__ char raw[];
    __nv_bfloat16* Ah = reinterpret_cast<__nv_bfloat16*>(raw);
    __nv_bfloat16* Al = Ah + 128 * TCS2;
    __nv_bfloat16* Bh = Al + 128 * TCS2;
    __nv_bfloat16* Bl = Bh + 128 * TCS2;
    float* obuf = reinterpret_cast<float*>(raw);

    const int tid = threadIdx.x;
    const int bn = blockIdx.x;
    const int bm = blockIdx.y;
    const int w  = tid >> 5;
    const int wm = w & 3;
    const int wn = w >> 2;

    const __nv_bfloat16* GWh = g_Wh + (size_t)3 * EMB * EMB;
    const __nv_bfloat16* GWl = g_Wl + (size_t)3 * EMB * EMB;

    wmma::fragment<wmma::accumulator, 16, 16, 16, float> acc[2][4];
#pragma unroll
    for (int im = 0; im < 2; im++)
#pragma unroll
        for (int jn = 0; jn < 4; jn++) wmma::fill_fragment(acc[im][jn], 0.f);

    for (int ks = 0; ks < EMB; ks += 64) {
        __syncthreads();
#pragma unroll
        for (int i = 0; i < 4; i++) {
            int idx = tid + i * 256;
            int row = idx >> 3;
            int seg = idx & 7;
            size_t ga = (size_t)(bm * 128 + row) * EMB + ks + seg * 8;
            size_t gb = (size_t)(bn * 128 + row) * EMB + ks + seg * 8;
            int so = row * TCS2 + seg * 8;
            *reinterpret_cast<uint4*>(Ah + so) = *reinterpret_cast<const uint4*>(g_Ah + ga);
            *reinterpret_cast<uint4*>(Al + so) = *reinterpret_cast<const uint4*>(g_Al + ga);
            *reinterpret_cast<uint4*>(Bh + so) = *reinterpret_cast<const uint4*>(GWh + gb);
            *reinterpret_cast<uint4*>(Bl + so) = *reinterpret_cast<const uint4*>(GWl + gb);
        }
        __syncthreads();

#pragma unroll
        for (int kk = 0; kk < 4; kk++) {
            wmma::fragment<wmma::matrix_a, 16, 16, 16, __nv_bfloat16, wmma::row_major> ah[2], al[2];
#pragma unroll
            for (int im = 0; im < 2; im++) {
                wmma::load_matrix_sync(ah[im], Ah + (wm * 32 + im * 16) * TCS2 + kk * 16, TCS2);
                wmma::load_matrix_sync(al[im], Al + (wm * 32 + im * 16) * TCS2 + kk * 16, TCS2);
            }
#pragma unroll
            for (int jn = 0; jn < 4; jn++) {
                wmma::fragment<wmma::matrix_b, 16, 16, 16, __nv_bfloat16, wmma::col_major> bh, bl;
                wmma::load_matrix_sync(bh, Bh + (wn * 64 + jn * 16) * TCS2 + kk * 16, TCS2);
                wmma::load_matrix_sync(bl, Bl + (wn * 64 + jn * 16) * TCS2 + kk * 16, TCS2);
#pragma unroll
                for (int im = 0; im < 2; im++) {
                    wmma::mma_sync(acc[im][jn], ah[im], bh, acc[im][jn]);
                    wmma::mma_sync(acc[im][jn], ah[im], bl, acc[im][jn]);
                    wmma::mma_sync(acc[im][jn], al[im], bh, acc[im][jn]);
                }
            }
        }
    }

#pragma unroll
    for (int half = 0; half < 2; half++) {
        __syncthreads();
        if (wn == half) {
#pragma unroll
            for (int im = 0; im < 2; im++)
#pragma unroll
                for (int jn = 0; jn < 4; jn++)
                    wmma::store_matrix_sync(obuf + (wm * 32 + im * 16) * OBS + jn * 16,
                                            acc[im][jn], OBS, wmma::mem_row_major);
        }
        __syncthreads();
#pragma unroll
        for (int it = 0; it < 8; it++) {
            int idx = tid + it * 256;
            int row = idx >> 4;
            int c4  = idx & 15;
            float4 v = *reinterpret_cast<const float4*>(&obuf[row * OBS + c4 * 4]);
            int colg = bn * 128 + half * 64 + c4 * 4;
            v.x += bias[colg + 0]; v.y += bias[colg + 1];
            v.z += bias[colg + 2]; v.w += bias[colg + 3];
            int ro = bm * 128 + row;
            int g = (ro & 2047) * B_SZ + (ro >> 11);
            *reinterpret_cast<float4*>(out + (size_t)g * EMB + colg) = v;
        }
    }
}

// ---------------------------------------------------------------------------
// Kernel 2: LSH hashing GEMM (64x128 tile) + guarded argmax.
// ---------------------------------------------------------------------------
__global__ __launch_bounds__(256) void hash_gemm(const float* __restrict__ lshW,
                                                 const float* __restrict__ lshb)
{
    __shared__ float As2h[2][16][130];
    __shared__ float Bsh[2][16][132];
    const int tid = threadIdx.x;
    const int bm = blockIdx.x;
    const int tensor = blockIdx.y;
    const int tx = tid & 15, ty = tid >> 4;

    const float* A = tensor ? g_K : g_Q;
    unsigned char* dst = tensor ? g_kh : g_qh;

    const int arr = tid >> 2, ak4 = tid & 3;
    const int br0 = (tid * 2) >> 2, bk40 = (tid * 2) & 3;
    const int br1 = (tid * 2 + 1) >> 2, bk41 = (tid * 2 + 1) & 3;
    const float* Abase = A + (size_t)(bm * 64 + arr) * 64 + ak4 * 4;
    const float* B0 = lshW + (size_t)br0 * 64 + bk40 * 4;
    const float* B1 = lshW + (size_t)br1 * 64 + bk41 * 4;

    float2 acc[4][4];
#pragma unroll
    for (int i = 0; i < 4; i++)
#pragma unroll
        for (int p = 0; p < 4; p++) acc[i][p] = make_float2(0.f, 0.f);

    float4 ra = *reinterpret_cast<const float4*>(Abase);
    float4 rb0 = *reinterpret_cast<const float4*>(B0);
    float4 rb1 = *reinterpret_cast<const float4*>(B1);
    {
        float va[4] = {ra.x, ra.y, ra.z, ra.w};
#pragma unroll
        for (int c = 0; c < 4; c++) {
            As2h[0][ak4 * 4 + c][2 * arr] = va[c];
            As2h[0][ak4 * 4 + c][2 * arr + 1] = va[c];
        }
        Bsh[0][bk40 * 4 + 0][br0] = rb0.x; Bsh[0][bk40 * 4 + 1][br0] = rb0.y;
        Bsh[0][bk40 * 4 + 2][br0] = rb0.z; Bsh[0][bk40 * 4 + 3][br0] = rb0.w;
        Bsh[0][bk41 * 4 + 0][br1] = rb1.x; Bsh[0][bk41 * 4 + 1][br1] = rb1.y;
        Bsh[0][bk41 * 4 + 2][br1] = rb1.z; Bsh[0][bk41 * 4 + 3][br1] = rb1.w;
    }
    __syncthreads();

    for (int s = 0; s < 4; s++) {
        const int cur = s & 1;
        if (s + 1 < 4) {
            ra  = *reinterpret_cast<const float4*>(Abase + (s + 1) * 16);
            rb0 = *reinterpret_cast<const float4*>(B0 + (s + 1) * 16);
            rb1 = *reinterpret_cast<const float4*>(B1 + (s + 1) * 16);
        }
#pragma unroll
        for (int k = 0; k < 16; k++) {
            float2 avd[4], bv2[4];
#pragma unroll
            for (int i = 0; i < 4; i++)
                avd[i] = *reinterpret_cast<const float2*>(&As2h[cur][k][2 * (ty * 4 + i)]);
#pragma unroll
            for (int p = 0; p < 4; p++)
                bv2[p] = *reinterpret_cast<const float2*>(&Bsh[cur][k][p * 32 + tx * 2]);
#pragma unroll
            for (int i = 0; i < 4; i++)
#pragma unroll
                for (int p = 0; p < 4; p++)
                    acc[i][p] = ffma2(avd[i], bv2[p], acc[i][p]);
        }
        if (s + 1 < 4) {
            __syncthreads();
            const int nxt = cur ^ 1;
            float va[4] = {ra.x, ra.y, ra.z, ra.w};
#pragma unroll
            for (int c = 0; c < 4; c++) {
                As2h[nxt][ak4 * 4 + c][2 * arr] = va[c];
                As2h[nxt][ak4 * 4 + c][2 * arr + 1] = va[c];
            }
            Bsh[nxt][bk40 * 4 + 0][br0] = rb0.x; Bsh[nxt][bk40 * 4 + 1][br0] = rb0.y;
            Bsh[nxt][bk40 * 4 + 2][br0] = rb0.z; Bsh[nxt][bk40 * 4 + 3][br0] = rb0.w;
            Bsh[nxt][bk41 * 4 + 0][br1] = rb1.x; Bsh[nxt][bk41 * 4 + 1][br1] = rb1.y;
            Bsh[nxt][bk41 * 4 + 2][br1] = rb1.z; Bsh[nxt][bk41 * 4 + 3][br1] = rb1.w;
            __syncthreads();
        }
    }

    float2 bb2[4];
#pragma unroll
    for (int p = 0; p < 4; p++)
        bb2[p] = *reinterpret_cast<const float2*>(lshb + p * 32 + tx * 2);

#pragma unroll
    for (int i = 0; i < 4; i++) {
        const int m  = bm * 64 + ty * 4 + i;
        const int r  = m >> 3, h = m & 7;
        const int nb = r >> 11, nt = r & 2047;
#pragma unroll
        for (int hh = 0; hh < 2; hh++) {
            float2 c0 = acc[i][2 * hh];
            float2 c1 = acc[i][2 * hh + 1];
            c0.x += bb2[2 * hh].x;     c0.y += bb2[2 * hh].y;
            c1.x += bb2[2 * hh + 1].x; c1.y += bb2[2 * hh + 1].y;
            float bvv = c0.x; int bi = tx * 2; float sec = -INFINITY;
            if (c0.y > bvv) { sec = bvv; bvv = c0.y; bi = tx * 2 + 1; }
            else sec = fmaxf(sec, c0.y);
            if (c1.x > bvv) { sec = bvv; bvv = c1.x; bi = 32 + tx * 2; }
            else sec = fmaxf(sec, c1.x);
            if (c1.y > bvv) { sec = bvv; bvv = c1.y; bi = 33 + tx * 2; }
            else sec = fmaxf(sec, c1.y);
#pragma unroll
            for (int off = 1; off < 16; off <<= 1) {
                float ov = __shfl_xor_sync(FULLMASK, bvv, off);
                int   oi = __shfl_xor_sync(FULLMASK, bi, off);
                float os = __shfl_xor_sync(FULLMASK, sec, off);
                if (ov > bvv || (ov == bvv && oi < bi)) {
                    sec = fmaxf(fmaxf(sec, os), bvv);
                    bvv = ov; bi = oi;
                } else {
                    sec = fmaxf(fmaxf(sec, os), ov);
                }
            }
            if (tx == 0) {
                dst[((hh * B_SZ + nb) * HEADS + h) * T_LEN + nt] = (unsigned char)bi;
                if (bvv - sec < TAU) {
                    int ix = atomicAdd(&g_nfix, 1);
                    if (ix < FIXCAP)
                        g_fix[ix] = m | (hh << 15) | (tensor << 16);
                }
            }
        }
    }
}

// ---------------------------------------------------------------------------
// Fixup: exact-fp32 recompute of flagged argmaxes. One warp per entry.
// Phase A is k-parallel: lane owns x[lane*16..+16) (coalesced), per-dim
// 16 FMA + 5-shfl reduce. Phase B as before.
// ---------------------------------------------------------------------------
__global__ __launch_bounds__(256) void hash_fixup(
    const float* __restrict__ query, const float* __restrict__ key,
    const float* __restrict__ Wq, const float* __restrict__ Wk,
    const float* __restrict__ bq, const float* __restrict__ bk,
    const float* __restrict__ lshW, const float* __restrict__ lshb)
{
    __shared__ float qsm[8][64];
    const int lw = threadIdx.x >> 5;
    const int lane = threadIdx.x & 31;
    const int wid = blockIdx.x * 8 + lw;
    const int nw = gridDim.x * 8;
    const int n = min(g_nfix, FIXCAP);

    for (int e = wid; e < n; e += nw) {
        int ent = g_fix[e];
        int m = ent & 0x7FFF;
        int hh = (ent >> 15) & 1;
        int tensor = (ent >> 16) & 1;
        int r = m >> 3, h = m & 7;
        const float* X = tensor ? key : query;
        const float* W = tensor ? Wk : Wq;
        const float* bias = tensor ? bk : bq;
        unsigned char* dst = tensor ? g_kh : g_qh;
        int srcr = (r & 1) * T_LEN + (r >> 1);
        const float* xrow = X + (size_t)srcr * EMB;

        // exact q head-slice, k-parallel
        float xr[16];
#pragma unroll
        for (int q4 = 0; q4 < 4; q4++) {
            float4 v = *reinterpret_cast<const float4*>(xrow + lane * 16 + q4 * 4);
            xr[q4 * 4 + 0] = v.x; xr[q4 * 4 + 1] = v.y;
            xr[q4 * 4 + 2] = v.z; xr[q4 * 4 + 3] = v.w;
        }
        for (int d = 0; d < 64; d++) {
            const float* wrow = W + (size_t)(h * 64 + d) * EMB + lane * 16;
            float p = 0.f;
#pragma unroll
            for (int q4 = 0; q4 < 4; q4++) {
                float4 wv = *reinterpret_cast<const float4*>(wrow + q4 * 4);
                p += xr[q4 * 4 + 0] * wv.x + xr[q4 * 4 + 1] * wv.y
                   + xr[q4 * 4 + 2] * wv.z + xr[q4 * 4 + 3] * wv.w;
            }
#pragma unroll
            for (int off = 16; off; off >>= 1)
                p += __shfl_xor_sync(FULLMASK, p, off);
            if (lane == 0) qsm[lw][d] = p + bias[h * 64 + d];
        }
        __syncwarp();

        // exact hash scores + argmax (ties -> lowest index)
        float s0 = lshb[hh * 64 + lane];
        float s1 = lshb[hh * 64 + lane + 32];
        const float* hw0 = lshW + ((size_t)hh * 64 + lane) * 64;
        const float* hw1 = lshW + ((size_t)hh * 64 + lane + 32) * 64;
        for (int d2 = 0; d2 < 64; d2++) {
            float qv = qsm[lw][d2];
            s0 += qv * hw0[d2];
            s1 += qv * hw1[d2];
        }
        float bvv = s0; int bd = lane;
        if (s1 > bvv) { bvv = s1; bd = lane + 32; }
#pragma unroll
        for (int off = 16; off; off >>= 1) {
            float ov = __shfl_xor_sync(FULLMASK, bvv, off);
            int   od = __shfl_xor_sync(FULLMASK, bd, off);
            if (ov > bvv || (ov == bvv && od < bd)) { bvv = ov; bd = od; }
        }
        if (lane == 0) {
            int nb = r >> 11, nt = r & 2047;
            dst[((hh * B_SZ + nb) * HEADS + h) * T_LEN + nt] = (unsigned char)bd;
        }
        __syncwarp();
    }
}

// ---------------------------------------------------------------------------
// Kernel 3: bucketize — grid (32 combos, 2 tensors)
// ---------------------------------------------------------------------------
__global__ __launch_bounds__(256) void bucketize_kernel()
{
    __shared__ int cnt[64];
    __shared__ int off[64];
    const int combo = blockIdx.x;
    const int tensor = blockIdx.y;
    const int tid = threadIdx.x;

    const unsigned char* hsrc = (tensor ? g_kh : g_qh) + combo * T_LEN;
    int* startp = tensor ? g_kstart[combo] : g_qstart[combo];
    unsigned short* listp = (tensor ? g_klist : g_qlist) + combo * T_LEN;

    if (tid < 64) cnt[tid] = 0;
    __syncthreads();

    for (int i = tid; i < T_LEN; i += 256)
        atomicAdd(&cnt[hsrc[i]], 1);
    __syncthreads();

    if (tid == 0) {
        int s = 0;
        for (int j = 0; j < 64; j++) { startp[j] = s; off[j] = s; s += cnt[j]; }
        startp[64] = s;
    }
    __syncthreads();

    for (int i = tid; i < T_LEN; i += 256) {
        int p = atomicAdd(&off[hsrc[i]], 1);
        listp[p] = (unsigned short)i;
    }
}

// ---------------------------------------------------------------------------
// Kernel 4: per-bucket flash attention, 32x32 tiles.
// ---------------------------------------------------------------------------
#define QS  68
#define KSK 34
#define KSP 33

__global__ __launch_bounds__(256) void attn_bucket_kernel()
{
    __shared__ float qsh[32 * QS];
    __shared__ float ksh[64 * KSK];
    __shared__ float vsh[32 * QS];
    __shared__ float psh[32 * KSP];
    __shared__ int   qid[32];

    const int bucket = blockIdx.x;
    const int combo  = blockIdx.y;
    const int hash = combo >> 4;
    const int b    = (combo >> 3) & 1;
    const int h    = combo & 7;
    const int tid  = threadIdx.x;
    const int tx = tid & 15, ty = tid >> 4;

    const int qs = g_qstart[combo][bucket];
    const int nq = g_qstart[combo][bucket + 1] - qs;
    if (nq == 0) return;
    const int ks = g_kstart[combo][bucket];
    const int kn = g_kstart[combo][bucket + 1] - ks;

    const unsigned short* qlist = g_qlist + combo * T_LEN;
    const unsigned short* klist = g_klist + combo * T_LEN;

    float* Op = g_att[hash] + (size_t)b * T_LEN * EMB + h * HDIM;

    if (bucket >= 32 || kn == 0) {
        for (int idx = tid; idx < nq * 16; idx += 256) {
            int qi = idx >> 4, sl = idx & 15;
            int t = qlist[qs + qi];
            *reinterpret_cast<float4*>(Op + (size_t)t * EMB + sl * 4) =
                make_float4(0.f, 0.f, 0.f, 0.f);
        }
        return;
    }

    const float* Qp = g_Q + (size_t)b * T_LEN * EMB + h * HDIM;
    const float* Kp = g_K + (size_t)b * T_LEN * EMB + h * HDIM;
    const float* Vp = g_V + (size_t)b * T_LEN * EMB + h * HDIM;

    for (int q0 = 0; q0 < nq; q0 += 32) {
        const int cq = min(32, nq - q0);
        __syncthreads();
        for (int task = tid; task < 512; task += 256) {
            int row = task >> 4, slot = task & 15;
            if (row < cq) {
                int t = qlist[qs + q0 + row];
                if (slot == 0) qid[row] = t;
                float4 v4 = *reinterpret_cast<const float4*>(Qp + (size_t)t * EMB + slot * 4);
                float* d = &qsh[row * QS + slot * 4];
                d[0] = v4.x; d[1] = v4.y; d[2] = v4.z; d[3] = v4.w;
            }
        }
        __syncthreads();

        float m[2], l[2], o[2][4];
#pragma unroll
        for (int i = 0; i < 2; i++) {
            m[i] = -INFINITY; l[i] = 0.f;
#pragma unroll
            for (int d = 0; d < 4; d++) o[i][d] = 0.f;
        }

        for (int k0 = 0; k0 < kn; k0 += 32) {
            const int cnk = min(32, kn - k0);
            __syncthreads();
            for (int task = tid; task < 512; task += 256) {
                int row = task >> 4, slot = task & 15;
                float* dv = &vsh[row * QS + slot * 4];
                if (row < cnk) {
                    int t = klist[ks + k0 + row];
                    float4 k4 = *reinterpret_cast<const float4*>(Kp + (size_t)t * EMB + slot * 4);
                    ksh[(slot * 4 + 0) * KSK + row] = k4.x;
                    ksh[(slot * 4 + 1) * KSK + row] = k4.y;
                    ksh[(slot * 4 + 2) * KSK + row] = k4.z;
                    ksh[(slot * 4 + 3) * KSK + row] = k4.w;
                    float4 v4 = *reinterpret_cast<const float4*>(Vp + (size_t)t * EMB + slot * 4);
                    dv[0] = v4.x; dv[1] = v4.y; dv[2] = v4.z; dv[3] = v4.w;
                } else {
                    dv[0] = 0.f; dv[1] = 0.f; dv[2] = 0.f; dv[3] = 0.f;
                }
            }
            __syncthreads();

            float s00 = 0.f, s01 = 0.f, s10 = 0.f, s11 = 0.f;
            const float* q0p = &qsh[(ty * 2 + 0) * QS];
            const float* q1p = &qsh[(ty * 2 + 1) * QS];
#pragma unroll 8
            for (int k = 0; k < 64; k += 2) {
                float2 a0 = *reinterpret_cast<const float2*>(&q0p[k]);
                float2 a1 = *reinterpret_cast<const float2*>(&q1p[k]);
                float2 b0 = *reinterpret_cast<const float2*>(&ksh[k * KSK + tx * 2]);
                float2 b1 = *reinterpret_cast<const float2*>(&ksh[(k + 1) * KSK + tx * 2]);
                s00 += a0.x * b0.x + a0.y * b1.x;
                s01 += a0.x * b0.y + a0.y * b1.y;
                s10 += a1.x * b0.x + a1.y * b1.x;
                s11 += a1.x * b0.y + a1.y * b1.y;
            }
            const bool c0 = (tx * 2 + 0) < cnk;
            const bool c1 = (tx * 2 + 1) < cnk;
            float s4[2][2];
            s4[0][0] = c0 ? s00 * 0.125f : -INFINITY;
            s4[0][1] = c1 ? s01 * 0.125f : -INFINITY;
            s4[1][0] = c0 ? s10 * 0.125f : -INFINITY;
            s4[1][1] = c1 ? s11 * 0.125f : -INFINITY;

#pragma unroll
            for (int i = 0; i < 2; i++) {
                float cm = fmaxf(s4[i][0], s4[i][1]);
#pragma unroll
                for (int off = 1; off < 16; off <<= 1)
                    cm = fmaxf(cm, __shfl_xor_sync(FULLMASK, cm, off));
                float mn = fmaxf(m[i], cm);
                float corr = __expf(m[i] - mn);
                m[i] = mn;
                float w0 = __expf(s4[i][0] - mn);
                float w1 = __expf(s4[i][1] - mn);
                s4[i][0] = w0; s4[i][1] = w1;
                float ps = w0 + w1;
#pragma unroll
                for (int off = 1; off < 16; off <<= 1)
                    ps += __shfl_xor_sync(FULLMASK, ps, off);
                l[i] = l[i] * corr + ps;
#pragma unroll
                for (int d = 0; d < 4; d++) o[i][d] *= corr;
            }
#pragma unroll
            for (int i = 0; i < 2; i++) {
                psh[(ty * 2 + i) * KSP + tx * 2 + 0] = s4[i][0];
                psh[(ty * 2 + i) * KSP + tx * 2 + 1] = s4[i][1];
            }
            __syncthreads();
            const float* p0 = &psh[(ty * 2 + 0) * KSP];
            const float* p1 = &psh[(ty * 2 + 1) * KSP];
#pragma unroll 8
            for (int j = 0; j < 32; j++) {
                float pv0 = p0[j];
                float pv1 = p1[j];
                float4 vv = *reinterpret_cast<const float4*>(&vsh[j * QS + tx * 4]);
                o[0][0] += pv0 * vv.x; o[0][1] += pv0 * vv.y;
                o[0][2] += pv0 * vv.z; o[0][3] += pv0 * vv.w;
                o[1][0] += pv1 * vv.x; o[1][1] += pv1 * vv.y;
                o[1][2] += pv1 * vv.z; o[1][3] += pv1 * vv.w;
            }
        }

#pragma unroll
        for (int i = 0; i < 2; i++) {
            int row = ty * 2 + i;
            if (row < cq) {
                float inv = 1.f / l[i];
                int t = qid[row];
                float4 v;
                v.x = o[i][0] * inv; v.y = o[i][1] * inv;
                v.z = o[i][2] * inv; v.w = o[i][3] * inv;
                *reinterpret_cast<float4*>(Op + (size_t)t * EMB + tx * 4) = v;
            }
        }
    }
}

// ---------------------------------------------------------------------------
extern "C" void kernel_launch(void* const* d_in, const int* in_sizes, int n_in,
                              void* d_out, int out_size)
{
    (void)in_sizes; (void)n_in; (void)out_size;
    const float* query = (const float*)d_in[0];
    const float* key   = (const float*)d_in[1];
    const float* value = (const float*)d_in[2];
    const float* Wq = (const float*)d_in[3];
    const float* bq = (const float*)d_in[4];
    const float* Wk = (const float*)d_in[5];
    const float* bk = (const float*)d_in[6];
    const float* Wv = (const float*)d_in[7];
    const float* bv = (const float*)d_in[8];
    const float* Wo = (const float*)d_in[9];
    const float* bo = (const float*)d_in[10];
    const float* lshW = (const float*)d_in[11];
    const float* lshb = (const float*)d_in[12];
    float* out = (float*)d_out;

    cudaFuncSetAttribute(gemm_tc_qkv, cudaFuncAttributeMaxDynamicSharedMemorySize, TC_SMEM2);
    cudaFuncSetAttribute(gemm_tc_out, cudaFuncAttributeMaxDynamicSharedMemorySize, TC_SMEM2);

    split_x_kernel<<<dim3(ROWS * 128 / 256, 3), 256>>>(query, key, value);
    split_w_kernel<<<dim3(EMB * 128 / 256, 4), 256>>>(Wq, Wk, Wv, Wo);

    gemm_tc_qkv<<<dim3(EMB / 128, ROWS / 128, 3), 256, TC_SMEM2>>>(bq, bk, bv);
    hash_gemm<<<dim3(512, 2), 256>>>(lshW, lshb);
    hash_fixup<<<64, 256>>>(query, key, Wq, Wk, bq, bk, lshW, lshb);
    bucketize_kernel<<<dim3(32, 2), 256>>>();
    attn_bucket_kernel<<<dim3(64, 32), 256>>>();

    split_att_kernel<<<ROWS * 128 / 256, 256>>>();
    gemm_tc_out<<<dim3(EMB / 128, ROWS / 128), 256, TC_SMEM2>>>(out, bo);
}

// round 16
// speedup vs baseline: 1.5315x; 1.0954x over previous
#include <cuda_runtime.h>
#include <cuda_bf16.h>
#include <mma.h>
#include <cstdint>

using namespace nvcuda;

#define T_LEN 2048
#define B_SZ  2
#define EMB   512
#define ROWS  4096       // B*T
#define HEADS 8
#define HDIM  64
#define NHASH 2
#define FULLMASK 0xffffffffu
#define FIXCAP 8192
#define TAU 1e-3f

// ---------------------------------------------------------------------------
// Scratch
// ---------------------------------------------------------------------------
__device__ float g_Q[ROWS * EMB];
__device__ float g_K[ROWS * EMB];
__device__ float g_V[ROWS * EMB];
__device__ unsigned char g_qh[NHASH * B_SZ * HEADS * T_LEN];
__device__ unsigned char g_kh[NHASH * B_SZ * HEADS * T_LEN];
__device__ float g_att[NHASH][ROWS * EMB];
__device__ int g_qstart[32][65];
__device__ int g_kstart[32][65];
__device__ unsigned short g_qlist[32 * T_LEN];
__device__ unsigned short g_klist[32 * T_LEN];
// pre-split bf16 operands: A slots 0=query,1=key,2=value (slot 0 reused for att)
__device__ __nv_bfloat16 g_Ah[3 * ROWS * EMB];
__device__ __nv_bfloat16 g_Al[3 * ROWS * EMB];
// W slots: 0=Wq, 1=Wk, 2=Wv, 3=Wo
__device__ __nv_bfloat16 g_Wh[4 * EMB * EMB];
__device__ __nv_bfloat16 g_Wl[4 * EMB * EMB];
// ambiguous-argmax fixup list
__device__ int g_nfix;
__device__ int g_fix[FIXCAP];

// ---------------------------------------------------------------------------
// f32x2 helper (exact-fp32 hash path)
// ---------------------------------------------------------------------------
__device__ __forceinline__ float2 ffma2(float2 a, float2 b, float2 c)
{
    unsigned long long ua = *reinterpret_cast<unsigned long long*>(&a);
    unsigned long long ub = *reinterpret_cast<unsigned long long*>(&b);
    unsigned long long uc = *reinterpret_cast<unsigned long long*>(&c);
    unsigned long long ud;
    asm("fma.rn.f32x2 %0, %1, %2, %3;" : "=l"(ud) : "l"(ua), "l"(ub), "l"(uc));
    return *reinterpret_cast<float2*>(&ud);
}

// ---------------------------------------------------------------------------
// Split kernels
// ---------------------------------------------------------------------------
__device__ __forceinline__ void split_store4(__nv_bfloat16* dh, __nv_bfloat16* dl,
                                             float4 v)
{
    float h0 = __bfloat162float(__float2bfloat16(v.x));
    float h1 = __bfloat162float(__float2bfloat16(v.y));
    float h2 = __bfloat162float(__float2bfloat16(v.z));
    float h3 = __bfloat162float(__float2bfloat16(v.w));
    __nv_bfloat162 a, b;
    a.x = __float2bfloat16(v.x); a.y = __float2bfloat16(v.y);
    b.x = __float2bfloat16(v.z); b.y = __float2bfloat16(v.w);
    *reinterpret_cast<__nv_bfloat162*>(dh)     = a;
    *reinterpret_cast<__nv_bfloat162*>(dh + 2) = b;
    __nv_bfloat162 c, d;
    c.x = __float2bfloat16(v.x - h0); c.y = __float2bfloat16(v.y - h1);
    d.x = __float2bfloat16(v.z - h2); d.y = __float2bfloat16(v.w - h3);
    *reinterpret_cast<__nv_bfloat162*>(dl)     = c;
    *reinterpret_cast<__nv_bfloat162*>(dl + 2) = d;
}

__global__ __launch_bounds__(256) void split_x_kernel(const float* __restrict__ query,
                                                      const float* __restrict__ key,
                                                      const float* __restrict__ value)
{
    const int t = blockIdx.y;
    if (blockIdx.x == 0 && t == 0 && threadIdx.x == 0) g_nfix = 0;
    int idx = blockIdx.x * 256 + threadIdx.x;
    int f = idx >> 7;
    int c = (idx & 127) * 4;
    int srcr = (f & 1) * T_LEN + (f >> 1);
    const float* X = (t == 0) ? query : (t == 1) ? key : value;
    float4 v = *reinterpret_cast<const float4*>(X + (size_t)srcr * EMB + c);
    size_t o = (size_t)t * ROWS * EMB + (size_t)f * EMB + c;
    split_store4(g_Ah + o, g_Al + o, v);
}

__global__ __launch_bounds__(256) void split_w_kernel(const float* __restrict__ Wq,
                                                      const float* __restrict__ Wk,
                                                      const float* __restrict__ Wv,
                                                      const float* __restrict__ Wo)
{
    const int wsel = blockIdx.y;
    int idx = blockIdx.x * 256 + threadIdx.x;
    int rr = idx >> 7;
    int c = (idx & 127) * 4;
    const float* W = (wsel == 0) ? Wq : (wsel == 1) ? Wk : (wsel == 2) ? Wv : Wo;
    float4 v = *reinterpret_cast<const float4*>(W + (size_t)rr * EMB + c);
    size_t o = (size_t)wsel * EMB * EMB + (size_t)rr * EMB + c;
    split_store4(g_Wh + o, g_Wl + o, v);
}

__global__ __launch_bounds__(256) void split_att_kernel()
{
    int idx = blockIdx.x * 256 + threadIdx.x;
    int f = idx >> 7;
    int c = (idx & 127) * 4;
    size_t o = (size_t)f * EMB + c;
    float4 x = *reinterpret_cast<const float4*>(&g_att[0][o]);
    float4 y = *reinterpret_cast<const float4*>(&g_att[1][o]);
    x.x = 0.5f * (x.x + y.x); x.y = 0.5f * (x.y + y.y);
    x.z = 0.5f * (x.z + y.z); x.w = 0.5f * (x.w + y.w);
    split_store4(g_Ah + o, g_Al + o, x);
}

// ---------------------------------------------------------------------------
// TC GEMM core, 2 CTA/SM.
// ---------------------------------------------------------------------------
#define TCS2 72
#define OBS  72
#define TC_SMEM2 (4 * 128 * TCS2 * 2)    // 73728 B

__global__ __launch_bounds__(256, 2) void gemm_tc_qkv(const float* __restrict__ bq,
                                                      const float* __restrict__ bk,
                                                      const float* __restrict__ bv)
{
    extern __shared__ char raw[];
    __nv_bfloat16* Ah = reinterpret_cast<__nv_bfloat16*>(raw);
    __nv_bfloat16* Al = Ah + 128 * TCS2;
    __nv_bfloat16* Bh = Al + 128 * TCS2;
    __nv_bfloat16* Bl = Bh + 128 * TCS2;
    float* obuf = reinterpret_cast<float*>(raw);

    const int tid = threadIdx.x;
    const int bn = blockIdx.x;
    const int bm = blockIdx.y;
    const int z  = blockIdx.z;
    const int w  = tid >> 5;
    const int wm = w & 3;
    const int wn = w >> 2;

    const __nv_bfloat16* GAh = g_Ah + (size_t)z * ROWS * EMB;
    const __nv_bfloat16* GAl = g_Al + (size_t)z * ROWS * EMB;
    const __nv_bfloat16* GWh = g_Wh + (size_t)z * EMB * EMB;
    const __nv_bfloat16* GWl = g_Wl + (size_t)z * EMB * EMB;
    const float* bias = (z == 0) ? bq : (z == 1) ? bk : bv;

    wmma::fragment<wmma::accumulator, 16, 16, 16, float> acc[2][4];
#pragma unroll
    for (int im = 0; im < 2; im++)
#pragma unroll
        for (int jn = 0; jn < 4; jn++) wmma::fill_fragment(acc[im][jn], 0.f);

    for (int ks = 0; ks < EMB; ks += 64) {
        __syncthreads();
#pragma unroll
        for (int i = 0; i < 4; i++) {
            int idx = tid + i * 256;
            int row = idx >> 3;
            int seg = idx & 7;
            size_t ga = (size_t)(bm * 128 + row) * EMB + ks + seg * 8;
            size_t gb = (size_t)(bn * 128 + row) * EMB + ks + seg * 8;
            int so = row * TCS2 + seg * 8;
            *reinterpret_cast<uint4*>(Ah + so) = *reinterpret_cast<const uint4*>(GAh + ga);
            *reinterpret_cast<uint4*>(Al + so) = *reinterpret_cast<const uint4*>(GAl + ga);
            *reinterpret_cast<uint4*>(Bh + so) = *reinterpret_cast<const uint4*>(GWh + gb);
            *reinterpret_cast<uint4*>(Bl + so) = *reinterpret_cast<const uint4*>(GWl + gb);
        }
        __syncthreads();

#pragma unroll
        for (int kk = 0; kk < 4; kk++) {
            wmma::fragment<wmma::matrix_a, 16, 16, 16, __nv_bfloat16, wmma::row_major> ah[2], al[2];
#pragma unroll
            for (int im = 0; im < 2; im++) {
                wmma::load_matrix_sync(ah[im], Ah + (wm * 32 + im * 16) * TCS2 + kk * 16, TCS2);
                wmma::load_matrix_sync(al[im], Al + (wm * 32 + im * 16) * TCS2 + kk * 16, TCS2);
            }
#pragma unroll
            for (int jn = 0; jn < 4; jn++) {
                wmma::fragment<wmma::matrix_b, 16, 16, 16, __nv_bfloat16, wmma::col_major> bh, bl;
                wmma::load_matrix_sync(bh, Bh + (wn * 64 + jn * 16) * TCS2 + kk * 16, TCS2);
                wmma::load_matrix_sync(bl, Bl + (wn * 64 + jn * 16) * TCS2 + kk * 16, TCS2);
#pragma unroll
                for (int im = 0; im < 2; im++) {
                    wmma::mma_sync(acc[im][jn], ah[im], bh, acc[im][jn]);
                    wmma::mma_sync(acc[im][jn], ah[im], bl, acc[im][jn]);
                    wmma::mma_sync(acc[im][jn], al[im], bh, acc[im][jn]);
                }
            }
        }
    }

    float* dstp = (z == 0) ? g_Q : (z == 1) ? g_K : g_V;

#pragma unroll
    for (int half = 0; half < 2; half++) {
        __syncthreads();
        if (wn == half) {
#pragma unroll
            for (int im = 0; im < 2; im++)
#pragma unroll
                for (int jn = 0; jn < 4; jn++)
                    wmma::store_matrix_sync(obuf + (wm * 32 + im * 16) * OBS + jn * 16,
                                            acc[im][jn], OBS, wmma::mem_row_major);
        }
        __syncthreads();
#pragma unroll
        for (int it = 0; it < 8; it++) {
            int idx = tid + it * 256;
            int row = idx >> 4;
            int c4  = idx & 15;
            float4 v = *reinterpret_cast<const float4*>(&obuf[row * OBS + c4 * 4]);
            int colg = bn * 128 + half * 64 + c4 * 4;
            v.x += bias[colg + 0]; v.y += bias[colg + 1];
            v.z += bias[colg + 2]; v.w += bias[colg + 3];
            int ro = bm * 128 + row;
            *reinterpret_cast<float4*>(dstp + (size_t)ro * EMB + colg) = v;
        }
    }
}

__global__ __launch_bounds__(256, 2) void gemm_tc_out(float* __restrict__ out,
                                                      const float* __restrict__ bias)
{
    extern __shared__ char raw[];
    __nv_bfloat16* Ah = reinterpret_cast<__nv_bfloat16*>(raw);
    __nv_bfloat16* Al = Ah + 128 * TCS2;
    __nv_bfloat16* Bh = Al + 128 * TCS2;
    __nv_bfloat16* Bl = Bh + 128 * TCS2;
    float* obuf = reinterpret_cast<float*>(raw);

    const int tid = threadIdx.x;
    const int bn = blockIdx.x;
    const int bm = blockIdx.y;
    const int w  = tid >> 5;
    const int wm = w & 3;
    const int wn = w >> 2;

    const __nv_bfloat16* GWh = g_Wh + (size_t)3 * EMB * EMB;
    const __nv_bfloat16* GWl = g_Wl + (size_t)3 * EMB * EMB;

    wmma::fragment<wmma::accumulator, 16, 16, 16, float> acc[2][4];
#pragma unroll
    for (int im = 0; im < 2; im++)
#pragma unroll
        for (int jn = 0; jn < 4; jn++) wmma::fill_fragment(acc[im][jn], 0.f);

    for (int ks = 0; ks < EMB; ks += 64) {
        __syncthreads();
#pragma unroll
        for (int i = 0; i < 4; i++) {
            int idx = tid + i * 256;
            int row = idx >> 3;
            int seg = idx & 7;
            size_t ga = (size_t)(bm * 128 + row) * EMB + ks + seg * 8;
            size_t gb = (size_t)(bn * 128 + row) * EMB + ks + seg * 8;
            int so = row * TCS2 + seg * 8;
            *reinterpret_cast<uint4*>(Ah + so) = *reinterpret_cast<const uint4*>(g_Ah + ga);
            *reinterpret_cast<uint4*>(Al + so) = *reinterpret_cast<const uint4*>(g_Al + ga);
            *reinterpret_cast<uint4*>(Bh + so) = *reinterpret_cast<const uint4*>(GWh + gb);
            *reinterpret_cast<uint4*>(Bl + so) = *reinterpret_cast<const uint4*>(GWl + gb);
        }
        __syncthreads();

#pragma unroll
        for (int kk = 0; kk < 4; kk++) {
            wmma::fragment<wmma::matrix_a, 16, 16, 16, __nv_bfloat16, wmma::row_major> ah[2], al[2];
#pragma unroll
            for (int im = 0; im < 2; im++) {
                wmma::load_matrix_sync(ah[im], Ah + (wm * 32 + im * 16) * TCS2 + kk * 16, TCS2);
                wmma::load_matrix_sync(al[im], Al + (wm * 32 + im * 16) * TCS2 + kk * 16, TCS2);
            }
#pragma unroll
            for (int jn = 0; jn < 4; jn++) {
                wmma::fragment<wmma::matrix_b, 16, 16, 16, __nv_bfloat16, wmma::col_major> bh, bl;
                wmma::load_matrix_sync(bh, Bh + (wn * 64 + jn * 16) * TCS2 + kk * 16, TCS2);
                wmma::load_matrix_sync(bl, Bl + (wn * 64 + jn * 16) * TCS2 + kk * 16, TCS2);
#pragma unroll
                for (int im = 0; im < 2; im++) {
                    wmma::mma_sync(acc[im][jn], ah[im], bh, acc[im][jn]);
                    wmma::mma_sync(acc[im][jn], ah[im], bl, acc[im][jn]);
                    wmma::mma_sync(acc[im][jn], al[im], bh, acc[im][jn]);
                }
            }
        }
    }

#pragma unroll
    for (int half = 0; half < 2; half++) {
        __syncthreads();
        if (wn == half) {
#pragma unroll
            for (int im = 0; im < 2; im++)
#pragma unroll
                for (int jn = 0; jn < 4; jn++)
                    wmma::store_matrix_sync(obuf + (wm * 32 + im * 16) * OBS + jn * 16,
                                            acc[im][jn], OBS, wmma::mem_row_major);
        }
        __syncthreads();
#pragma unroll
        for (int it = 0; it < 8; it++) {
            int idx = tid + it * 256;
            int row = idx >> 4;
            int c4  = idx & 15;
            float4 v = *reinterpret_cast<const float4*>(&obuf[row * OBS + c4 * 4]);
            int colg = bn * 128 + half * 64 + c4 * 4;
            v.x += bias[colg + 0]; v.y += bias[colg + 1];
            v.z += bias[colg + 2]; v.w += bias[colg + 3];
            int ro = bm * 128 + row;
            int g = (ro & 2047) * B_SZ + (ro >> 11);
            *reinterpret_cast<float4*>(out + (size_t)g * EMB + colg) = v;
        }
    }
}

// ---------------------------------------------------------------------------
// Kernel 2: LSH hashing GEMM + guarded argmax.
// ---------------------------------------------------------------------------
__global__ __launch_bounds__(256) void hash_gemm(const float* __restrict__ lshW,
                                                 const float* __restrict__ lshb)
{
    __shared__ float As2h[2][16][130];
    __shared__ float Bsh[2][16][132];
    const int tid = threadIdx.x;
    const int bm = blockIdx.x;
    const int tensor = blockIdx.y;
    const int tx = tid & 15, ty = tid >> 4;

    const float* A = tensor ? g_K : g_Q;
    unsigned char* dst = tensor ? g_kh : g_qh;

    const int arr = tid >> 2, ak4 = tid & 3;
    const int br0 = (tid * 2) >> 2, bk40 = (tid * 2) & 3;
    const int br1 = (tid * 2 + 1) >> 2, bk41 = (tid * 2 + 1) & 3;
    const float* Abase = A + (size_t)(bm * 64 + arr) * 64 + ak4 * 4;
    const float* B0 = lshW + (size_t)br0 * 64 + bk40 * 4;
    const float* B1 = lshW + (size_t)br1 * 64 + bk41 * 4;

    float2 acc[4][4];
#pragma unroll
    for (int i = 0; i < 4; i++)
#pragma unroll
        for (int p = 0; p < 4; p++) acc[i][p] = make_float2(0.f, 0.f);

    float4 ra = *reinterpret_cast<const float4*>(Abase);
    float4 rb0 = *reinterpret_cast<const float4*>(B0);
    float4 rb1 = *reinterpret_cast<const float4*>(B1);
    {
        float va[4] = {ra.x, ra.y, ra.z, ra.w};
#pragma unroll
        for (int c = 0; c < 4; c++) {
            As2h[0][ak4 * 4 + c][2 * arr] = va[c];
            As2h[0][ak4 * 4 + c][2 * arr + 1] = va[c];
        }
        Bsh[0][bk40 * 4 + 0][br0] = rb0.x; Bsh[0][bk40 * 4 + 1][br0] = rb0.y;
        Bsh[0][bk40 * 4 + 2][br0] = rb0.z; Bsh[0][bk40 * 4 + 3][br0] = rb0.w;
        Bsh[0][bk41 * 4 + 0][br1] = rb1.x; Bsh[0][bk41 * 4 + 1][br1] = rb1.y;
        Bsh[0][bk41 * 4 + 2][br1] = rb1.z; Bsh[0][bk41 * 4 + 3][br1] = rb1.w;
    }
    __syncthreads();

    for (int s = 0; s < 4; s++) {
        const int cur = s & 1;
        if (s + 1 < 4) {
            ra  = *reinterpret_cast<const float4*>(Abase + (s + 1) * 16);
            rb0 = *reinterpret_cast<const float4*>(B0 + (s + 1) * 16);
            rb1 = *reinterpret_cast<const float4*>(B1 + (s + 1) * 16);
        }
#pragma unroll
        for (int k = 0; k < 16; k++) {
            float2 avd[4], bv2[4];
#pragma unroll
            for (int i = 0; i < 4; i++)
                avd[i] = *reinterpret_cast<const float2*>(&As2h[cur][k][2 * (ty * 4 + i)]);
#pragma unroll
            for (int p = 0; p < 4; p++)
                bv2[p] = *reinterpret_cast<const float2*>(&Bsh[cur][k][p * 32 + tx * 2]);
#pragma unroll
            for (int i = 0; i < 4; i++)
#pragma unroll
                for (int p = 0; p < 4; p++)
                    acc[i][p] = ffma2(avd[i], bv2[p], acc[i][p]);
        }
        if (s + 1 < 4) {
            __syncthreads();
            const int nxt = cur ^ 1;
            float va[4] = {ra.x, ra.y, ra.z, ra.w};
#pragma unroll
            for (int c = 0; c < 4; c++) {
                As2h[nxt][ak4 * 4 + c][2 * arr] = va[c];
                As2h[nxt][ak4 * 4 + c][2 * arr + 1] = va[c];
            }
            Bsh[nxt][bk40 * 4 + 0][br0] = rb0.x; Bsh[nxt][bk40 * 4 + 1][br0] = rb0.y;
            Bsh[nxt][bk40 * 4 + 2][br0] = rb0.z; Bsh[nxt][bk40 * 4 + 3][br0] = rb0.w;
            Bsh[nxt][bk41 * 4 + 0][br1] = rb1.x; Bsh[nxt][bk41 * 4 + 1][br1] = rb1.y;
            Bsh[nxt][bk41 * 4 + 2][br1] = rb1.z; Bsh[nxt][bk41 * 4 + 3][br1] = rb1.w;
            __syncthreads();
        }
    }

    float2 bb2[4];
#pragma unroll
    for (int p = 0; p < 4; p++)
        bb2[p] = *reinterpret_cast<const float2*>(lshb + p * 32 + tx * 2);

#pragma unroll
    for (int i = 0; i < 4; i++) {
        const int m  = bm * 64 + ty * 4 + i;
        const int r  = m >> 3, h = m & 7;
        const int nb = r >> 11, nt = r & 2047;
#pragma unroll
        for (int hh = 0; hh < 2; hh++) {
            float2 c0 = acc[i][2 * hh];
            float2 c1 = acc[i][2 * hh + 1];
            c0.x += bb2[2 * hh].x;     c0.y += bb2[2 * hh].y;
            c1.x += bb2[2 * hh + 1].x; c1.y += bb2[2 * hh + 1].y;
            float bvv = c0.x; int bi = tx * 2; float sec = -INFINITY;
            if (c0.y > bvv) { sec = bvv; bvv = c0.y; bi = tx * 2 + 1; }
            else sec = fmaxf(sec, c0.y);
            if (c1.x > bvv) { sec = bvv; bvv = c1.x; bi = 32 + tx * 2; }
            else sec = fmaxf(sec, c1.x);
            if (c1.y > bvv) { sec = bvv; bvv = c1.y; bi = 33 + tx * 2; }
            else sec = fmaxf(sec, c1.y);
#pragma unroll
            for (int off = 1; off < 16; off <<= 1) {
                float ov = __shfl_xor_sync(FULLMASK, bvv, off);
                int   oi = __shfl_xor_sync(FULLMASK, bi, off);
                float os = __shfl_xor_sync(FULLMASK, sec, off);
                if (ov > bvv || (ov == bvv && oi < bi)) {
                    sec = fmaxf(fmaxf(sec, os), bvv);
                    bvv = ov; bi = oi;
                } else {
                    sec = fmaxf(fmaxf(sec, os), ov);
                }
            }
            if (tx == 0) {
                dst[((hh * B_SZ + nb) * HEADS + h) * T_LEN + nt] = (unsigned char)bi;
                if (bvv - sec < TAU) {
                    int ix = atomicAdd(&g_nfix, 1);
                    if (ix < FIXCAP)
                        g_fix[ix] = m | (hh << 15) | (tensor << 16);
                }
            }
        }
    }
}

// ---------------------------------------------------------------------------
// Fixup: exact-fp32 recompute of flagged argmaxes. One warp per entry.
// ---------------------------------------------------------------------------
__global__ __launch_bounds__(256) void hash_fixup(
    const float* __restrict__ query, const float* __restrict__ key,
    const float* __restrict__ Wq, const float* __restrict__ Wk,
    const float* __restrict__ bq, const float* __restrict__ bk,
    const float* __restrict__ lshW, const float* __restrict__ lshb)
{
    __shared__ float qsm[8][64];
    const int lw = threadIdx.x >> 5;
    const int lane = threadIdx.x & 31;
    const int wid = blockIdx.x * 8 + lw;
    const int nw = gridDim.x * 8;
    const int n = min(g_nfix, FIXCAP);

    for (int e = wid; e < n; e += nw) {
        int ent = g_fix[e];
        int m = ent & 0x7FFF;
        int hh = (ent >> 15) & 1;
        int tensor = (ent >> 16) & 1;
        int r = m >> 3, h = m & 7;
        const float* X = tensor ? key : query;
        const float* W = tensor ? Wk : Wq;
        const float* bias = tensor ? bk : bq;
        unsigned char* dst = tensor ? g_kh : g_qh;
        int srcr = (r & 1) * T_LEN + (r >> 1);
        const float* xrow = X + (size_t)srcr * EMB;

        float xr[16];
#pragma unroll
        for (int q4 = 0; q4 < 4; q4++) {
            float4 v = *reinterpret_cast<const float4*>(xrow + lane * 16 + q4 * 4);
            xr[q4 * 4 + 0] = v.x; xr[q4 * 4 + 1] = v.y;
            xr[q4 * 4 + 2] = v.z; xr[q4 * 4 + 3] = v.w;
        }
        for (int d = 0; d < 64; d++) {
            const float* wrow = W + (size_t)(h * 64 + d) * EMB + lane * 16;
            float p = 0.f;
#pragma unroll
            for (int q4 = 0; q4 < 4; q4++) {
                float4 wv = *reinterpret_cast<const float4*>(wrow + q4 * 4);
                p += xr[q4 * 4 + 0] * wv.x + xr[q4 * 4 + 1] * wv.y
                   + xr[q4 * 4 + 2] * wv.z + xr[q4 * 4 + 3] * wv.w;
            }
#pragma unroll
            for (int off = 16; off; off >>= 1)
                p += __shfl_xor_sync(FULLMASK, p, off);
            if (lane == 0) qsm[lw][d] = p + bias[h * 64 + d];
        }
        __syncwarp();

        float s0 = lshb[hh * 64 + lane];
        float s1 = lshb[hh * 64 + lane + 32];
        const float* hw0 = lshW + ((size_t)hh * 64 + lane) * 64;
        const float* hw1 = lshW + ((size_t)hh * 64 + lane + 32) * 64;
        for (int d2 = 0; d2 < 64; d2++) {
            float qv = qsm[lw][d2];
            s0 += qv * hw0[d2];
            s1 += qv * hw1[d2];
        }
        float bvv = s0; int bd = lane;
        if (s1 > bvv) { bvv = s1; bd = lane + 32; }
#pragma unroll
        for (int off = 16; off; off >>= 1) {
            float ov = __shfl_xor_sync(FULLMASK, bvv, off);
            int   od = __shfl_xor_sync(FULLMASK, bd, off);
            if (ov > bvv || (ov == bvv && od < bd)) { bvv = ov; bd = od; }
        }
        if (lane == 0) {
            int nb = r >> 11, nt = r & 2047;
            dst[((hh * B_SZ + nb) * HEADS + h) * T_LEN + nt] = (unsigned char)bd;
        }
        __syncwarp();
    }
}

// ---------------------------------------------------------------------------
// Kernel 3: bucketize — grid (32 combos, 2 tensors)
// ---------------------------------------------------------------------------
__global__ __launch_bounds__(256) void bucketize_kernel()
{
    __shared__ int cnt[64];
    __shared__ int off[64];
    const int combo = blockIdx.x;
    const int tensor = blockIdx.y;
    const int tid = threadIdx.x;

    const unsigned char* hsrc = (tensor ? g_kh : g_qh) + combo * T_LEN;
    int* startp = tensor ? g_kstart[combo] : g_qstart[combo];
    unsigned short* listp = (tensor ? g_klist : g_qlist) + combo * T_LEN;

    if (tid < 64) cnt[tid] = 0;
    __syncthreads();

    for (int i = tid; i < T_LEN; i += 256)
        atomicAdd(&cnt[hsrc[i]], 1);
    __syncthreads();

    if (tid == 0) {
        int s = 0;
        for (int j = 0; j < 64; j++) { startp[j] = s; off[j] = s; s += cnt[j]; }
        startp[64] = s;
    }
    __syncthreads();

    for (int i = tid; i < T_LEN; i += 256) {
        int p = atomicAdd(&off[hsrc[i]], 1);
        listp[p] = (unsigned short)i;
    }
}

// ---------------------------------------------------------------------------
// Kernel 4: per-bucket flash attention, 32x32 tiles.
// grid = (256, 32): blockIdx.x = bucket*4 + qchunk; each block handles
// q-tiles q0 = qchunk*32, qchunk*32+128, ... (balances large buckets).
// ---------------------------------------------------------------------------
#define QS  68
#define KSK 34
#define KSP 33

__global__ __launch_bounds__(256) void attn_bucket_kernel()
{
    __shared__ float qsh[32 * QS];
    __shared__ float ksh[64 * KSK];
    __shared__ float vsh[32 * QS];
    __shared__ float psh[32 * KSP];
    __shared__ int   qid[32];

    const int bucket = blockIdx.x >> 2;
    const int qt     = blockIdx.x & 3;
    const int combo  = blockIdx.y;
    const int hash = combo >> 4;
    const int b    = (combo >> 3) & 1;
    const int h    = combo & 7;
    const int tid  = threadIdx.x;
    const int tx = tid & 15, ty = tid >> 4;

    const int qs = g_qstart[combo][bucket];
    const int nq = g_qstart[combo][bucket + 1] - qs;
    if (nq <= qt * 32) return;
    const int ks = g_kstart[combo][bucket];
    const int kn = g_kstart[combo][bucket + 1] - ks;

    const unsigned short* qlist = g_qlist + combo * T_LEN;
    const unsigned short* klist = g_klist + combo * T_LEN;

    float* Op = g_att[hash] + (size_t)b * T_LEN * EMB + h * HDIM;

    if (bucket >= 32 || kn == 0) {
        for (int q0 = qt * 32; q0 < nq; q0 += 128) {
            const int cq = min(32, nq - q0);
            for (int idx = tid; idx < cq * 16; idx += 256) {
                int qi = idx >> 4, sl = idx & 15;
                int t = qlist[qs + q0 + qi];
                *reinterpret_cast<float4*>(Op + (size_t)t * EMB + sl * 4) =
                    make_float4(0.f, 0.f, 0.f, 0.f);
            }
        }
        return;
    }

    const float* Qp = g_Q + (size_t)b * T_LEN * EMB + h * HDIM;
    const float* Kp = g_K + (size_t)b * T_LEN * EMB + h * HDIM;
    const float* Vp = g_V + (size_t)b * T_LEN * EMB + h * HDIM;

    for (int q0 = qt * 32; q0 < nq; q0 += 128) {
        const int cq = min(32, nq - q0);
        __syncthreads();
        for (int task = tid; task < 512; task += 256) {
            int row = task >> 4, slot = task & 15;
            if (row < cq) {
                int t = qlist[qs + q0 + row];
                if (slot == 0) qid[row] = t;
                float4 v4 = *reinterpret_cast<const float4*>(Qp + (size_t)t * EMB + slot * 4);
                float* d = &qsh[row * QS + slot * 4];
                d[0] = v4.x; d[1] = v4.y; d[2] = v4.z; d[3] = v4.w;
            }
        }
        __syncthreads();

        float m[2], l[2], o[2][4];
#pragma unroll
        for (int i = 0; i < 2; i++) {
            m[i] = -INFINITY; l[i] = 0.f;
#pragma unroll
            for (int d = 0; d < 4; d++) o[i][d] = 0.f;
        }

        for (int k0 = 0; k0 < kn; k0 += 32) {
            const int cnk = min(32, kn - k0);
            __syncthreads();
            for (int task = tid; task < 512; task += 256) {
                int row = task >> 4, slot = task & 15;
                float* dv = &vsh[row * QS + slot * 4];
                if (row < cnk) {
                    int t = klist[ks + k0 + row];
                    float4 k4 = *reinterpret_cast<const float4*>(Kp + (size_t)t * EMB + slot * 4);
                    ksh[(slot * 4 + 0) * KSK + row] = k4.x;
                    ksh[(slot * 4 + 1) * KSK + row] = k4.y;
                    ksh[(slot * 4 + 2) * KSK + row] = k4.z;
                    ksh[(slot * 4 + 3) * KSK + row] = k4.w;
                    float4 v4 = *reinterpret_cast<const float4*>(Vp + (size_t)t * EMB + slot * 4);
                    dv[0] = v4.x; dv[1] = v4.y; dv[2] = v4.z; dv[3] = v4.w;
                } else {
                    dv[0] = 0.f; dv[1] = 0.f; dv[2] = 0.f; dv[3] = 0.f;
                }
            }
            __syncthreads();

            float s00 = 0.f, s01 = 0.f, s10 = 0.f, s11 = 0.f;
            const float* q0p = &qsh[(ty * 2 + 0) * QS];
            const float* q1p = &qsh[(ty * 2 + 1) * QS];
#pragma unroll 8
            for (int k = 0; k < 64; k += 2) {
                float2 a0 = *reinterpret_cast<const float2*>(&q0p[k]);
                float2 a1 = *reinterpret_cast<const float2*>(&q1p[k]);
                float2 b0 = *reinterpret_cast<const float2*>(&ksh[k * KSK + tx * 2]);
                float2 b1 = *reinterpret_cast<const float2*>(&ksh[(k + 1) * KSK + tx * 2]);
                s00 += a0.x * b0.x + a0.y * b1.x;
                s01 += a0.x * b0.y + a0.y * b1.y;
                s10 += a1.x * b0.x + a1.y * b1.x;
                s11 += a1.x * b0.y + a1.y * b1.y;
            }
            const bool c0 = (tx * 2 + 0) < cnk;
            const bool c1 = (tx * 2 + 1) < cnk;
            float s4[2][2];
            s4[0][0] = c0 ? s00 * 0.125f : -INFINITY;
            s4[0][1] = c1 ? s01 * 0.125f : -INFINITY;
            s4[1][0] = c0 ? s10 * 0.125f : -INFINITY;
            s4[1][1] = c1 ? s11 * 0.125f : -INFINITY;

#pragma unroll
            for (int i = 0; i < 2; i++) {
                float cm = fmaxf(s4[i][0], s4[i][1]);
#pragma unroll
                for (int off = 1; off < 16; off <<= 1)
                    cm = fmaxf(cm, __shfl_xor_sync(FULLMASK, cm, off));
                float mn = fmaxf(m[i], cm);
                float corr = __expf(m[i] - mn);
                m[i] = mn;
                float w0 = __expf(s4[i][0] - mn);
                float w1 = __expf(s4[i][1] - mn);
                s4[i][0] = w0; s4[i][1] = w1;
                float ps = w0 + w1;
#pragma unroll
                for (int off = 1; off < 16; off <<= 1)
                    ps += __shfl_xor_sync(FULLMASK, ps, off);
                l[i] = l[i] * corr + ps;
#pragma unroll
                for (int d = 0; d < 4; d++) o[i][d] *= corr;
            }
#pragma unroll
            for (int i = 0; i < 2; i++) {
                psh[(ty * 2 + i) * KSP + tx * 2 + 0] = s4[i][0];
                psh[(ty * 2 + i) * KSP + tx * 2 + 1] = s4[i][1];
            }
            __syncthreads();
            const float* p0 = &psh[(ty * 2 + 0) * KSP];
            const float* p1 = &psh[(ty * 2 + 1) * KSP];
#pragma unroll 8
            for (int j = 0; j < 32; j++) {
                float pv0 = p0[j];
                float pv1 = p1[j];
                float4 vv = *reinterpret_cast<const float4*>(&vsh[j * QS + tx * 4]);
                o[0][0] += pv0 * vv.x; o[0][1] += pv0 * vv.y;
                o[0][2] += pv0 * vv.z; o[0][3] += pv0 * vv.w;
                o[1][0] += pv1 * vv.x; o[1][1] += pv1 * vv.y;
                o[1][2] += pv1 * vv.z; o[1][3] += pv1 * vv.w;
            }
        }

#pragma unroll
        for (int i = 0; i < 2; i++) {
            int row = ty * 2 + i;
            if (row < cq) {
                float inv = 1.f / l[i];
                int t = qid[row];
                float4 v;
                v.x = o[i][0] * inv; v.y = o[i][1] * inv;
                v.z = o[i][2] * inv; v.w = o[i][3] * inv;
                *reinterpret_cast<float4*>(Op + (size_t)t * EMB + tx * 4) = v;
            }
        }
    }
}

// ---------------------------------------------------------------------------
extern "C" void kernel_launch(void* const* d_in, const int* in_sizes, int n_in,
                              void* d_out, int out_size)
{
    (void)in_sizes; (void)n_in; (void)out_size;
    const float* query = (const float*)d_in[0];
    const float* key   = (const float*)d_in[1];
    const float* value = (const float*)d_in[2];
    const float* Wq = (const float*)d_in[3];
    const float* bq = (const float*)d_in[4];
    const float* Wk = (const float*)d_in[5];
    const float* bk = (const float*)d_in[6];
    const float* Wv = (const float*)d_in[7];
    const float* bv = (const float*)d_in[8];
    const float* Wo = (const float*)d_in[9];
    const float* bo = (const float*)d_in[10];
    const float* lshW = (const float*)d_in[11];
    const float* lshb = (const float*)d_in[12];
    float* out = (float*)d_out;

    cudaFuncSetAttribute(gemm_tc_qkv, cudaFuncAttributeMaxDynamicSharedMemorySize, TC_SMEM2);
    cudaFuncSetAttribute(gemm_tc_out, cudaFuncAttributeMaxDynamicSharedMemorySize, TC_SMEM2);

    split_x_kernel<<<dim3(ROWS * 128 / 256, 3), 256>>>(query, key, value);
    split_w_kernel<<<dim3(EMB * 128 / 256, 4), 256>>>(Wq, Wk, Wv, Wo);

    gemm_tc_qkv<<<dim3(EMB / 128, ROWS / 128, 3), 256, TC_SMEM2>>>(bq, bk, bv);
    hash_gemm<<<dim3(512, 2), 256>>>(lshW, lshb);
    hash_fixup<<<64, 256>>>(query, key, Wq, Wk, bq, bk, lshW, lshb);
    bucketize_kernel<<<dim3(32, 2), 256>>>();
    attn_bucket_kernel<<<dim3(256, 32), 256>>>();

    split_att_kernel<<<ROWS * 128 / 256, 256>>>();
    gemm_tc_out<<<dim3(EMB / 128, ROWS / 128), 256, TC_SMEM2>>>(out, bo);
}

// round 17
// speedup vs baseline: 1.5368x; 1.0035x over previous
#include <cuda_runtime.h>
#include <cuda_bf16.h>
#include <mma.h>
#include <cstdint>

using namespace nvcuda;

#define T_LEN 2048
#define B_SZ  2
#define EMB   512
#define ROWS  4096       // B*T
#define HEADS 8
#define HDIM  64
#define NHASH 2
#define FULLMASK 0xffffffffu
#define FIXCAP 8192
#define TAU 1e-3f

// ---------------------------------------------------------------------------
// Scratch
// ---------------------------------------------------------------------------
__device__ float g_Q[ROWS * EMB];
__device__ float g_K[ROWS * EMB];
__device__ float g_V[ROWS * EMB];
__device__ unsigned char g_qh[NHASH * B_SZ * HEADS * T_LEN];
__device__ unsigned char g_kh[NHASH * B_SZ * HEADS * T_LEN];
__device__ float g_att[NHASH][ROWS * EMB];
__device__ int g_qstart[32][65];
__device__ int g_kstart[32][65];
__device__ unsigned short g_qlist[32 * T_LEN];
__device__ unsigned short g_klist[32 * T_LEN];
// pre-split bf16 operands: A slots 0=query,1=key,2=value.
// After gemm_tc_qkv, slots 0/1 are overwritten with split(g_Q)/split(g_K)
// for the TC hash; slot 0 is later overwritten with the att average.
__device__ __nv_bfloat16 g_Ah[3 * ROWS * EMB];
__device__ __nv_bfloat16 g_Al[3 * ROWS * EMB];
// W slots: 0=Wq, 1=Wk, 2=Wv, 3=Wo
__device__ __nv_bfloat16 g_Wh[4 * EMB * EMB];
__device__ __nv_bfloat16 g_Wl[4 * EMB * EMB];
// ambiguous-argmax fixup list
__device__ int g_nfix;
__device__ int g_fix[FIXCAP];

// ---------------------------------------------------------------------------
// Split helpers
// ---------------------------------------------------------------------------
__device__ __forceinline__ void split_store4(__nv_bfloat16* dh, __nv_bfloat16* dl,
                                             float4 v)
{
    float h0 = __bfloat162float(__float2bfloat16(v.x));
    float h1 = __bfloat162float(__float2bfloat16(v.y));
    float h2 = __bfloat162float(__float2bfloat16(v.z));
    float h3 = __bfloat162float(__float2bfloat16(v.w));
    __nv_bfloat162 a, b;
    a.x = __float2bfloat16(v.x); a.y = __float2bfloat16(v.y);
    b.x = __float2bfloat16(v.z); b.y = __float2bfloat16(v.w);
    *reinterpret_cast<__nv_bfloat162*>(dh)     = a;
    *reinterpret_cast<__nv_bfloat162*>(dh + 2) = b;
    __nv_bfloat162 c, d;
    c.x = __float2bfloat16(v.x - h0); c.y = __float2bfloat16(v.y - h1);
    d.x = __float2bfloat16(v.z - h2); d.y = __float2bfloat16(v.w - h3);
    *reinterpret_cast<__nv_bfloat162*>(dl)     = c;
    *reinterpret_cast<__nv_bfloat162*>(dl + 2) = d;
}

__global__ __launch_bounds__(256) void split_x_kernel(const float* __restrict__ query,
                                                      const float* __restrict__ key,
                                                      const float* __restrict__ value)
{
    const int t = blockIdx.y;
    if (blockIdx.x == 0 && t == 0 && threadIdx.x == 0) g_nfix = 0;
    int idx = blockIdx.x * 256 + threadIdx.x;
    int f = idx >> 7;
    int c = (idx & 127) * 4;
    int srcr = (f & 1) * T_LEN + (f >> 1);
    const float* X = (t == 0) ? query : (t == 1) ? key : value;
    float4 v = *reinterpret_cast<const float4*>(X + (size_t)srcr * EMB + c);
    size_t o = (size_t)t * ROWS * EMB + (size_t)f * EMB + c;
    split_store4(g_Ah + o, g_Al + o, v);
}

__global__ __launch_bounds__(256) void split_w_kernel(const float* __restrict__ Wq,
                                                      const float* __restrict__ Wk,
                                                      const float* __restrict__ Wv,
                                                      const float* __restrict__ Wo)
{
    const int wsel = blockIdx.y;
    int idx = blockIdx.x * 256 + threadIdx.x;
    int rr = idx >> 7;
    int c = (idx & 127) * 4;
    const float* W = (wsel == 0) ? Wq : (wsel == 1) ? Wk : (wsel == 2) ? Wv : Wo;
    float4 v = *reinterpret_cast<const float4*>(W + (size_t)rr * EMB + c);
    size_t o = (size_t)wsel * EMB * EMB + (size_t)rr * EMB + c;
    split_store4(g_Wh + o, g_Wl + o, v);
}

// split projected Q (slot 0) / K (slot 1) for the TC hash
__global__ __launch_bounds__(256) void split_qk_kernel()
{
    const int t = blockIdx.y;   // 0 = Q, 1 = K
    int idx = blockIdx.x * 256 + threadIdx.x;
    size_t o4 = (size_t)idx * 4;
    const float* X = t ? g_K : g_Q;
    float4 v = *reinterpret_cast<const float4*>(X + o4);
    size_t o = (size_t)t * ROWS * EMB + o4;
    split_store4(g_Ah + o, g_Al + o, v);
}

__global__ __launch_bounds__(256) void split_att_kernel()
{
    int idx = blockIdx.x * 256 + threadIdx.x;
    size_t o = (size_t)idx * 4;
    float4 x = *reinterpret_cast<const float4*>(&g_att[0][o]);
    float4 y = *reinterpret_cast<const float4*>(&g_att[1][o]);
    x.x = 0.5f * (x.x + y.x); x.y = 0.5f * (x.y + y.y);
    x.z = 0.5f * (x.z + y.z); x.w = 0.5f * (x.w + y.w);
    split_store4(g_Ah + o, g_Al + o, x);
}

// ---------------------------------------------------------------------------
// TC GEMM core, 2 CTA/SM.
// ---------------------------------------------------------------------------
#define TCS2 72
#define OBS  72
#define TC_SMEM2 (4 * 128 * TCS2 * 2)    // 73728 B

__global__ __launch_bounds__(256, 2) void gemm_tc_qkv(const float* __restrict__ bq,
                                                      const float* __restrict__ bk,
                                                      const float* __restrict__ bv)
{
    extern __shared__ char raw[];
    __nv_bfloat16* Ah = reinterpret_cast<__nv_bfloat16*>(raw);
    __nv_bfloat16* Al = Ah + 128 * TCS2;
    __nv_bfloat16* Bh = Al + 128 * TCS2;
    __nv_bfloat16* Bl = Bh + 128 * TCS2;
    float* obuf = reinterpret_cast<float*>(raw);

    const int tid = threadIdx.x;
    const int bn = blockIdx.x;
    const int bm = blockIdx.y;
    const int z  = blockIdx.z;
    const int w  = tid >> 5;
    const int wm = w & 3;
    const int wn = w >> 2;

    const __nv_bfloat16* GAh = g_Ah + (size_t)z * ROWS * EMB;
    const __nv_bfloat16* GAl = g_Al + (size_t)z * ROWS * EMB;
    const __nv_bfloat16* GWh = g_Wh + (size_t)z * EMB * EMB;
    const __nv_bfloat16* GWl = g_Wl + (size_t)z * EMB * EMB;
    const float* bias = (z == 0) ? bq : (z == 1) ? bk : bv;

    wmma::fragment<wmma::accumulator, 16, 16, 16, float> acc[2][4];
#pragma unroll
    for (int im = 0; im < 2; im++)
#pragma unroll
        for (int jn = 0; jn < 4; jn++) wmma::fill_fragment(acc[im][jn], 0.f);

    for (int ks = 0; ks < EMB; ks += 64) {
        __syncthreads();
#pragma unroll
        for (int i = 0; i < 4; i++) {
            int idx = tid + i * 256;
            int row = idx >> 3;
            int seg = idx & 7;
            size_t ga = (size_t)(bm * 128 + row) * EMB + ks + seg * 8;
            size_t gb = (size_t)(bn * 128 + row) * EMB + ks + seg * 8;
            int so = row * TCS2 + seg * 8;
            *reinterpret_cast<uint4*>(Ah + so) = *reinterpret_cast<const uint4*>(GAh + ga);
            *reinterpret_cast<uint4*>(Al + so) = *reinterpret_cast<const uint4*>(GAl + ga);
            *reinterpret_cast<uint4*>(Bh + so) = *reinterpret_cast<const uint4*>(GWh + gb);
            *reinterpret_cast<uint4*>(Bl + so) = *reinterpret_cast<const uint4*>(GWl + gb);
        }
        __syncthreads();

#pragma unroll
        for (int kk = 0; kk < 4; kk++) {
            wmma::fragment<wmma::matrix_a, 16, 16, 16, __nv_bfloat16, wmma::row_major> ah[2], al[2];
#pragma unroll
            for (int im = 0; im < 2; im++) {
                wmma::load_matrix_sync(ah[im], Ah + (wm * 32 + im * 16) * TCS2 + kk * 16, TCS2);
                wmma::load_matrix_sync(al[im], Al + (wm * 32 + im * 16) * TCS2 + kk * 16, TCS2);
            }
#pragma unroll
            for (int jn = 0; jn < 4; jn++) {
                wmma::fragment<wmma::matrix_b, 16, 16, 16, __nv_bfloat16, wmma::col_major> bh, bl;
                wmma::load_matrix_sync(bh, Bh + (wn * 64 + jn * 16) * TCS2 + kk * 16, TCS2);
                wmma::load_matrix_sync(bl, Bl + (wn * 64 + jn * 16) * TCS2 + kk * 16, TCS2);
#pragma unroll
                for (int im = 0; im < 2; im++) {
                    wmma::mma_sync(acc[im][jn], ah[im], bh, acc[im][jn]);
                    wmma::mma_sync(acc[im][jn], ah[im], bl, acc[im][jn]);
                    wmma::mma_sync(acc[im][jn], al[im], bh, acc[im][jn]);
                }
            }
        }
    }

    float* dstp = (z == 0) ? g_Q : (z == 1) ? g_K : g_V;

#pragma unroll
    for (int half = 0; half < 2; half++) {
        __syncthreads();
        if (wn == half) {
#pragma unroll
            for (int im = 0; im < 2; im++)
#pragma unroll
                for (int jn = 0; jn < 4; jn++)
                    wmma::store_matrix_sync(obuf + (wm * 32 + im * 16) * OBS + jn * 16,
                                            acc[im][jn], OBS, wmma::mem_row_major);
        }
        __syncthreads();
#pragma unroll
        for (int it = 0; it < 8; it++) {
            int idx = tid + it * 256;
            int row = idx >> 4;
            int c4  = idx & 15;
            float4 v = *reinterpret_cast<const float4*>(&obuf[row * OBS + c4 * 4]);
            int colg = bn * 128 + half * 64 + c4 * 4;
            v.x += bias[colg + 0]; v.y += bias[colg + 1];
            v.z += bias[colg + 2]; v.w += bias[colg + 3];
            int ro = bm * 128 + row;
            *reinterpret_cast<float4*>(dstp + (size_t)ro * EMB + colg) = v;
        }
    }
}

__global__ __launch_bounds__(256, 2) void gemm_tc_out(float* __restrict__ out,
                                                      const float* __restrict__ bias)
{
    extern __shared__ char raw[];
    __nv_bfloat16* Ah = reinterpret_cast<__nv_bfloat16*>(raw);
    __nv_bfloat16* Al = Ah + 128 * TCS2;
    __nv_bfloat16* Bh = Al + 128 * TCS2;
    __nv_bfloat16* Bl = Bh + 128 * TCS2;
    float* obuf = reinterpret_cast<float*>(raw);

    const int tid = threadIdx.x;
    const int bn = blockIdx.x;
    const int bm = blockIdx.y;
    const int w  = tid >> 5;
    const int wm = w & 3;
    const int wn = w >> 2;

    const __nv_bfloat16* GWh = g_Wh + (size_t)3 * EMB * EMB;
    const __nv_bfloat16* GWl = g_Wl + (size_t)3 * EMB * EMB;

    wmma::fragment<wmma::accumulator, 16, 16, 16, float> acc[2][4];
#pragma unroll
    for (int im = 0; im < 2; im++)
#pragma unroll
        for (int jn = 0; jn < 4; jn++) wmma::fill_fragment(acc[im][jn], 0.f);

    for (int ks = 0; ks < EMB; ks += 64) {
        __syncthreads();
#pragma unroll
        for (int i = 0; i < 4; i++) {
            int idx = tid + i * 256;
            int row = idx >> 3;
            int seg = idx & 7;
            size_t ga = (size_t)(bm * 128 + row) * EMB + ks + seg * 8;
            size_t gb = (size_t)(bn * 128 + row) * EMB + ks + seg * 8;
            int so = row * TCS2 + seg * 8;
            *reinterpret_cast<uint4*>(Ah + so) = *reinterpret_cast<const uint4*>(g_Ah + ga);
            *reinterpret_cast<uint4*>(Al + so) = *reinterpret_cast<const uint4*>(g_Al + ga);
            *reinterpret_cast<uint4*>(Bh + so) = *reinterpret_cast<const uint4*>(GWh + gb);
            *reinterpret_cast<uint4*>(Bl + so) = *reinterpret_cast<const uint4*>(GWl + gb);
        }
        __syncthreads();

#pragma unroll
        for (int kk = 0; kk < 4; kk++) {
            wmma::fragment<wmma::matrix_a, 16, 16, 16, __nv_bfloat16, wmma::row_major> ah[2], al[2];
#pragma unroll
            for (int im = 0; im < 2; im++) {
                wmma::load_matrix_sync(ah[im], Ah + (wm * 32 + im * 16) * TCS2 + kk * 16, TCS2);
                wmma::load_matrix_sync(al[im], Al + (wm * 32 + im * 16) * TCS2 + kk * 16, TCS2);
            }
#pragma unroll
            for (int jn = 0; jn < 4; jn++) {
                wmma::fragment<wmma::matrix_b, 16, 16, 16, __nv_bfloat16, wmma::col_major> bh, bl;
                wmma::load_matrix_sync(bh, Bh + (wn * 64 + jn * 16) * TCS2 + kk * 16, TCS2);
                wmma::load_matrix_sync(bl, Bl + (wn * 64 + jn * 16) * TCS2 + kk * 16, TCS2);
#pragma unroll
                for (int im = 0; im < 2; im++) {
                    wmma::mma_sync(acc[im][jn], ah[im], bh, acc[im][jn]);
                    wmma::mma_sync(acc[im][jn], ah[im], bl, acc[im][jn]);
                    wmma::mma_sync(acc[im][jn], al[im], bh, acc[im][jn]);
                }
            }
        }
    }

#pragma unroll
    for (int half = 0; half < 2; half++) {
        __syncthreads();
        if (wn == half) {
#pragma unroll
            for (int im = 0; im < 2; im++)
#pragma unroll
                for (int jn = 0; jn < 4; jn++)
                    wmma::store_matrix_sync(obuf + (wm * 32 + im * 16) * OBS + jn * 16,
                                            acc[im][jn], OBS, wmma::mem_row_major);
        }
        __syncthreads();
#pragma unroll
        for (int it = 0; it < 8; it++) {
            int idx = tid + it * 256;
            int row = idx >> 4;
            int c4  = idx & 15;
            float4 v = *reinterpret_cast<const float4*>(&obuf[row * OBS + c4 * 4]);
            int colg = bn * 128 + half * 64 + c4 * 4;
            v.x += bias[colg + 0]; v.y += bias[colg + 1];
            v.z += bias[colg + 2]; v.w += bias[colg + 3];
            int ro = bm * 128 + row;
            int g = (ro & 2047) * B_SZ + (ro >> 11);
            *reinterpret_cast<float4*>(out + (size_t)g * EMB + colg) = v;
        }
    }
}

// ---------------------------------------------------------------------------
// TC hash: S[128 rows x 128 dims] = A[128x64] @ lshW^T (split-bf16, 3 MMAs),
// then smem argmax with top-2 guard. A = split(g_Q/g_K) viewed [32768][64].
// grid = (256 m-tiles, 2 tensors). Scores exact enough: guard + fixup covers.
// ---------------------------------------------------------------------------
#define HOB 136   // fp32 score stage stride

__global__ __launch_bounds__(256, 2) void hash_tc(const float* __restrict__ lshW,
                                                  const float* __restrict__ lshb)
{
    extern __shared__ char raw[];
    __nv_bfloat16* Ah = reinterpret_cast<__nv_bfloat16*>(raw);
    __nv_bfloat16* Al = Ah + 128 * TCS2;
    __nv_bfloat16* Bh = Al + 128 * TCS2;
    __nv_bfloat16* Bl = Bh + 128 * TCS2;
    float* obuf = reinterpret_cast<float*>(raw);          // [128][HOB]

    const int tid = threadIdx.x;
    const int bm = blockIdx.x;        // 0..255
    const int tensor = blockIdx.y;    // 0 = Q, 1 = K
    const int w  = tid >> 5;
    const int wm = w & 3;
    const int wn = w >> 2;

    const __nv_bfloat16* GAh = g_Ah + (size_t)tensor * ROWS * EMB;
    const __nv_bfloat16* GAl = g_Al + (size_t)tensor * ROWS * EMB;
    unsigned char* dst = tensor ? g_kh : g_qh;

    // stage A (128 rows x 64 k): 1024 uint4 per array
#pragma unroll
    for (int i = 0; i < 4; i++) {
        int idx = tid + i * 256;
        int row = idx >> 3;
        int seg = idx & 7;
        size_t ga = (size_t)(bm * 128 + row) * 64 + seg * 8;
        int so = row * TCS2 + seg * 8;
        *reinterpret_cast<uint4*>(Ah + so) = *reinterpret_cast<const uint4*>(GAh + ga);
        *reinterpret_cast<uint4*>(Al + so) = *reinterpret_cast<const uint4*>(GAl + ga);
    }
    // convert lshW (128 dims x 64 k) to hi/lo
    for (int idx = tid; idx < 128 * 64; idx += 256) {
        int d = idx >> 6, k = idx & 63;
        float v = lshW[idx];
        __nv_bfloat16 h = __float2bfloat16(v);
        Bh[d * TCS2 + k] = h;
        Bl[d * TCS2 + k] = __float2bfloat16(v - __bfloat162float(h));
    }
    __syncthreads();

    wmma::fragment<wmma::accumulator, 16, 16, 16, float> acc[2][4];
#pragma unroll
    for (int im = 0; im < 2; im++)
#pragma unroll
        for (int jn = 0; jn < 4; jn++) wmma::fill_fragment(acc[im][jn], 0.f);

#pragma unroll
    for (int kk = 0; kk < 4; kk++) {
        wmma::fragment<wmma::matrix_a, 16, 16, 16, __nv_bfloat16, wmma::row_major> ah[2], al[2];
#pragma unroll
        for (int im = 0; im < 2; im++) {
            wmma::load_matrix_sync(ah[im], Ah + (wm * 32 + im * 16) * TCS2 + kk * 16, TCS2);
            wmma::load_matrix_sync(al[im], Al + (wm * 32 + im * 16) * TCS2 + kk * 16, TCS2);
        }
#pragma unroll
        for (int jn = 0; jn < 4; jn++) {
            wmma::fragment<wmma::matrix_b, 16, 16, 16, __nv_bfloat16, wmma::col_major> bh, bl;
            wmma::load_matrix_sync(bh, Bh + (wn * 64 + jn * 16) * TCS2 + kk * 16, TCS2);
            wmma::load_matrix_sync(bl, Bl + (wn * 64 + jn * 16) * TCS2 + kk * 16, TCS2);
#pragma unroll
            for (int im = 0; im < 2; im++) {
                wmma::mma_sync(acc[im][jn], ah[im], bh, acc[im][jn]);
                wmma::mma_sync(acc[im][jn], ah[im], bl, acc[im][jn]);
                wmma::mma_sync(acc[im][jn], al[im], bh, acc[im][jn]);
            }
        }
    }

    __syncthreads();   // done reading smem operands; reuse as score stage
#pragma unroll
    for (int im = 0; im < 2; im++)
#pragma unroll
        for (int jn = 0; jn < 4; jn++)
            wmma::store_matrix_sync(obuf + (wm * 32 + im * 16) * HOB + wn * 64 + jn * 16,
                                    acc[im][jn], HOB, wmma::mem_row_major);
    __syncthreads();

    // argmax epilogue: thread owns (row = tid>>1, hh = tid&1)
    {
        const int row = tid >> 1;
        const int hh  = tid & 1;
        const float* sp = &obuf[row * HOB + hh * 64];
        const float* bp = lshb + hh * 64;
        float bvv = -INFINITY, sec = -INFINITY;
        int bi = 0;
#pragma unroll 8
        for (int d = 0; d < 64; d++) {
            float s = sp[d] + bp[d];
            if (s > bvv) { sec = bvv; bvv = s; bi = d; }
            else if (s > sec) sec = s;
        }
        const int m  = bm * 128 + row;
        const int r  = m >> 3, h = m & 7;
        const int nb = r >> 11, nt = r & 2047;
        dst[((hh * B_SZ + nb) * HEADS + h) * T_LEN + nt] = (unsigned char)bi;
        if (bvv - sec < TAU) {
            int ix = atomicAdd(&g_nfix, 1);
            if (ix < FIXCAP)
                g_fix[ix] = m | (hh << 15) | (tensor << 16);
        }
    }
}

// ---------------------------------------------------------------------------
// Fixup: exact-fp32 recompute of flagged argmaxes. One warp per entry.
// ---------------------------------------------------------------------------
__global__ __launch_bounds__(256) void hash_fixup(
    const float* __restrict__ query, const float* __restrict__ key,
    const float* __restrict__ Wq, const float* __restrict__ Wk,
    const float* __restrict__ bq, const float* __restrict__ bk,
    const float* __restrict__ lshW, const float* __restrict__ lshb)
{
    __shared__ float qsm[8][64];
    const int lw = threadIdx.x >> 5;
    const int lane = threadIdx.x & 31;
    const int wid = blockIdx.x * 8 + lw;
    const int nw = gridDim.x * 8;
    const int n = min(g_nfix, FIXCAP);

    for (int e = wid; e < n; e += nw) {
        int ent = g_fix[e];
        int m = ent & 0x7FFF;
        int hh = (ent >> 15) & 1;
        int tensor = (ent >> 16) & 1;
        int r = m >> 3, h = m & 7;
        const float* X = tensor ? key : query;
        const float* W = tensor ? Wk : Wq;
        const float* bias = tensor ? bk : bq;
        unsigned char* dst = tensor ? g_kh : g_qh;
        int srcr = (r & 1) * T_LEN + (r >> 1);
        const float* xrow = X + (size_t)srcr * EMB;

        float xr[16];
#pragma unroll
        for (int q4 = 0; q4 < 4; q4++) {
            float4 v = *reinterpret_cast<const float4*>(xrow + lane * 16 + q4 * 4);
            xr[q4 * 4 + 0] = v.x; xr[q4 * 4 + 1] = v.y;
            xr[q4 * 4 + 2] = v.z; xr[q4 * 4 + 3] = v.w;
        }
        for (int d = 0; d < 64; d++) {
            const float* wrow = W + (size_t)(h * 64 + d) * EMB + lane * 16;
            float p = 0.f;
#pragma unroll
            for (int q4 = 0; q4 < 4; q4++) {
                float4 wv = *reinterpret_cast<const float4*>(wrow + q4 * 4);
                p += xr[q4 * 4 + 0] * wv.x + xr[q4 * 4 + 1] * wv.y
                   + xr[q4 * 4 + 2] * wv.z + xr[q4 * 4 + 3] * wv.w;
            }
#pragma unroll
            for (int off = 16; off; off >>= 1)
                p += __shfl_xor_sync(FULLMASK, p, off);
            if (lane == 0) qsm[lw][d] = p + bias[h * 64 + d];
        }
        __syncwarp();

        float s0 = lshb[hh * 64 + lane];
        float s1 = lshb[hh * 64 + lane + 32];
        const float* hw0 = lshW + ((size_t)hh * 64 + lane) * 64;
        const float* hw1 = lshW + ((size_t)hh * 64 + lane + 32) * 64;
        for (int d2 = 0; d2 < 64; d2++) {
            float qv = qsm[lw][d2];
            s0 += qv * hw0[d2];
            s1 += qv * hw1[d2];
        }
        float bvv = s0; int bd = lane;
        if (s1 > bvv) { bvv = s1; bd = lane + 32; }
#pragma unroll
        for (int off = 16; off; off >>= 1) {
            float ov = __shfl_xor_sync(FULLMASK, bvv, off);
            int   od = __shfl_xor_sync(FULLMASK, bd, off);
            if (ov > bvv || (ov == bvv && od < bd)) { bvv = ov; bd = od; }
        }
        if (lane == 0) {
            int nb = r >> 11, nt = r & 2047;
            dst[((hh * B_SZ + nb) * HEADS + h) * T_LEN + nt] = (unsigned char)bd;
        }
        __syncwarp();
    }
}

// ---------------------------------------------------------------------------
// Kernel 3: bucketize — grid (32 combos, 2 tensors)
// ---------------------------------------------------------------------------
__global__ __launch_bounds__(256) void bucketize_kernel()
{
    __shared__ int cnt[64];
    __shared__ int off[64];
    const int combo = blockIdx.x;
    const int tensor = blockIdx.y;
    const int tid = threadIdx.x;

    const unsigned char* hsrc = (tensor ? g_kh : g_qh) + combo * T_LEN;
    int* startp = tensor ? g_kstart[combo] : g_qstart[combo];
    unsigned short* listp = (tensor ? g_klist : g_qlist) + combo * T_LEN;

    if (tid < 64) cnt[tid] = 0;
    __syncthreads();

    for (int i = tid; i < T_LEN; i += 256)
        atomicAdd(&cnt[hsrc[i]], 1);
    __syncthreads();

    if (tid == 0) {
        int s = 0;
        for (int j = 0; j < 64; j++) { startp[j] = s; off[j] = s; s += cnt[j]; }
        startp[64] = s;
    }
    __syncthreads();

    for (int i = tid; i < T_LEN; i += 256) {
        int p = atomicAdd(&off[hsrc[i]], 1);
        listp[p] = (unsigned short)i;
    }
}

// ---------------------------------------------------------------------------
// Kernel 4: per-bucket flash attention, 32x32 tiles, q-chunk balanced.
// ---------------------------------------------------------------------------
#define QS  68
#define KSK 34
#define KSP 33

__global__ __launch_bounds__(256) void attn_bucket_kernel()
{
    __shared__ float qsh[32 * QS];
    __shared__ float ksh[64 * KSK];
    __shared__ float vsh[32 * QS];
    __shared__ float psh[32 * KSP];
    __shared__ int   qid[32];

    const int bucket = blockIdx.x >> 2;
    const int qt     = blockIdx.x & 3;
    const int combo  = blockIdx.y;
    const int hash = combo >> 4;
    const int b    = (combo >> 3) & 1;
    const int h    = combo & 7;
    const int tid  = threadIdx.x;
    const int tx = tid & 15, ty = tid >> 4;

    const int qs = g_qstart[combo][bucket];
    const int nq = g_qstart[combo][bucket + 1] - qs;
    if (nq <= qt * 32) return;
    const int ks = g_kstart[combo][bucket];
    const int kn = g_kstart[combo][bucket + 1] - ks;

    const unsigned short* qlist = g_qlist + combo * T_LEN;
    const unsigned short* klist = g_klist + combo * T_LEN;

    float* Op = g_att[hash] + (size_t)b * T_LEN * EMB + h * HDIM;

    if (bucket >= 32 || kn == 0) {
        for (int q0 = qt * 32; q0 < nq; q0 += 128) {
            const int cq = min(32, nq - q0);
            for (int idx = tid; idx < cq * 16; idx += 256) {
                int qi = idx >> 4, sl = idx & 15;
                int t = qlist[qs + q0 + qi];
                *reinterpret_cast<float4*>(Op + (size_t)t * EMB + sl * 4) =
                    make_float4(0.f, 0.f, 0.f, 0.f);
            }
        }
        return;
    }

    const float* Qp = g_Q + (size_t)b * T_LEN * EMB + h * HDIM;
    const float* Kp = g_K + (size_t)b * T_LEN * EMB + h * HDIM;
    const float* Vp = g_V + (size_t)b * T_LEN * EMB + h * HDIM;

    for (int q0 = qt * 32; q0 < nq; q0 += 128) {
        const int cq = min(32, nq - q0);
        __syncthreads();
        for (int task = tid; task < 512; task += 256) {
            int row = task >> 4, slot = task & 15;
            if (row < cq) {
                int t = qlist[qs + q0 + row];
                if (slot == 0) qid[row] = t;
                float4 v4 = *reinterpret_cast<const float4*>(Qp + (size_t)t * EMB + slot * 4);
                float* d = &qsh[row * QS + slot * 4];
                d[0] = v4.x; d[1] = v4.y; d[2] = v4.z; d[3] = v4.w;
            }
        }
        __syncthreads();

        float m[2], l[2], o[2][4];
#pragma unroll
        for (int i = 0; i < 2; i++) {
            m[i] = -INFINITY; l[i] = 0.f;
#pragma unroll
            for (int d = 0; d < 4; d++) o[i][d] = 0.f;
        }

        for (int k0 = 0; k0 < kn; k0 += 32) {
            const int cnk = min(32, kn - k0);
            __syncthreads();
            for (int task = tid; task < 512; task += 256) {
                int row = task >> 4, slot = task & 15;
                float* dv = &vsh[row * QS + slot * 4];
                if (row < cnk) {
                    int t = klist[ks + k0 + row];
                    float4 k4 = *reinterpret_cast<const float4*>(Kp + (size_t)t * EMB + slot * 4);
                    ksh[(slot * 4 + 0) * KSK + row] = k4.x;
                    ksh[(slot * 4 + 1) * KSK + row] = k4.y;
                    ksh[(slot * 4 + 2) * KSK + row] = k4.z;
                    ksh[(slot * 4 + 3) * KSK + row] = k4.w;
                    float4 v4 = *reinterpret_cast<const float4*>(Vp + (size_t)t * EMB + slot * 4);
                    dv[0] = v4.x; dv[1] = v4.y; dv[2] = v4.z; dv[3] = v4.w;
                } else {
                    dv[0] = 0.f; dv[1] = 0.f; dv[2] = 0.f; dv[3] = 0.f;
                }
            }
            __syncthreads();

            float s00 = 0.f, s01 = 0.f, s10 = 0.f, s11 = 0.f;
            const float* q0p = &qsh[(ty * 2 + 0) * QS];
            const float* q1p = &qsh[(ty * 2 + 1) * QS];
#pragma unroll 8
            for (int k = 0; k < 64; k += 2) {
                float2 a0 = *reinterpret_cast<const float2*>(&q0p[k]);
                float2 a1 = *reinterpret_cast<const float2*>(&q1p[k]);
                float2 b0 = *reinterpret_cast<const float2*>(&ksh[k * KSK + tx * 2]);
                float2 b1 = *reinterpret_cast<const float2*>(&ksh[(k + 1) * KSK + tx * 2]);
                s00 += a0.x * b0.x + a0.y * b1.x;
                s01 += a0.x * b0.y + a0.y * b1.y;
                s10 += a1.x * b0.x + a1.y * b1.x;
                s11 += a1.x * b0.y + a1.y * b1.y;
            }
            const bool c0 = (tx * 2 + 0) < cnk;
            const bool c1 = (tx * 2 + 1) < cnk;
            float s4[2][2];
            s4[0][0] = c0 ? s00 * 0.125f : -INFINITY;
            s4[0][1] = c1 ? s01 * 0.125f : -INFINITY;
            s4[1][0] = c0 ? s10 * 0.125f : -INFINITY;
            s4[1][1] = c1 ? s11 * 0.125f : -INFINITY;

#pragma unroll
            for (int i = 0; i < 2; i++) {
                float cm = fmaxf(s4[i][0], s4[i][1]);
#pragma unroll
                for (int off = 1; off < 16; off <<= 1)
                    cm = fmaxf(cm, __shfl_xor_sync(FULLMASK, cm, off));
                float mn = fmaxf(m[i], cm);
                float corr = __expf(m[i] - mn);
                m[i] = mn;
                float w0 = __expf(s4[i][0] - mn);
                float w1 = __expf(s4[i][1] - mn);
                s4[i][0] = w0; s4[i][1] = w1;
                float ps = w0 + w1;
#pragma unroll
                for (int off = 1; off < 16; off <<= 1)
                    ps += __shfl_xor_sync(FULLMASK, ps, off);
                l[i] = l[i] * corr + ps;
#pragma unroll
                for (int d = 0; d < 4; d++) o[i][d] *= corr;
            }
#pragma unroll
            for (int i = 0; i < 2; i++) {
                psh[(ty * 2 + i) * KSP + tx * 2 + 0] = s4[i][0];
                psh[(ty * 2 + i) * KSP + tx * 2 + 1] = s4[i][1];
            }
            __syncthreads();
            const float* p0 = &psh[(ty * 2 + 0) * KSP];
            const float* p1 = &psh[(ty * 2 + 1) * KSP];
#pragma unroll 8
            for (int j = 0; j < 32; j++) {
                float pv0 = p0[j];
                float pv1 = p1[j];
                float4 vv = *reinterpret_cast<const float4*>(&vsh[j * QS + tx * 4]);
                o[0][0] += pv0 * vv.x; o[0][1] += pv0 * vv.y;
                o[0][2] += pv0 * vv.z; o[0][3] += pv0 * vv.w;
                o[1][0] += pv1 * vv.x; o[1][1] += pv1 * vv.y;
                o[1][2] += pv1 * vv.z; o[1][3] += pv1 * vv.w;
            }
        }

#pragma unroll
        for (int i = 0; i < 2; i++) {
            int row = ty * 2 + i;
            if (row < cq) {
                float inv = 1.f / l[i];
                int t = qid[row];
                float4 v;
                v.x = o[i][0] * inv; v.y = o[i][1] * inv;
                v.z = o[i][2] * inv; v.w = o[i][3] * inv;
                *reinterpret_cast<float4*>(Op + (size_t)t * EMB + tx * 4) = v;
            }
        }
    }
}

// ---------------------------------------------------------------------------
extern "C" void kernel_launch(void* const* d_in, const int* in_sizes, int n_in,
                              void* d_out, int out_size)
{
    (void)in_sizes; (void)n_in; (void)out_size;
    const float* query = (const float*)d_in[0];
    const float* key   = (const float*)d_in[1];
    const float* value = (const float*)d_in[2];
    const float* Wq = (const float*)d_in[3];
    const float* bq = (const float*)d_in[4];
    const float* Wk = (const float*)d_in[5];
    const float* bk = (const float*)d_in[6];
    const float* Wv = (const float*)d_in[7];
    const float* bv = (const float*)d_in[8];
    const float* Wo = (const float*)d_in[9];
    const float* bo = (const float*)d_in[10];
    const float* lshW = (const float*)d_in[11];
    const float* lshb = (const float*)d_in[12];
    float* out = (float*)d_out;

    cudaFuncSetAttribute(gemm_tc_qkv, cudaFuncAttributeMaxDynamicSharedMemorySize, TC_SMEM2);
    cudaFuncSetAttribute(gemm_tc_out, cudaFuncAttributeMaxDynamicSharedMemorySize, TC_SMEM2);
    cudaFuncSetAttribute(hash_tc, cudaFuncAttributeMaxDynamicSharedMemorySize, TC_SMEM2);

    split_x_kernel<<<dim3(ROWS * 128 / 256, 3), 256>>>(query, key, value);
    split_w_kernel<<<dim3(EMB * 128 / 256, 4), 256>>>(Wq, Wk, Wv, Wo);

    gemm_tc_qkv<<<dim3(EMB / 128, ROWS / 128, 3), 256, TC_SMEM2>>>(bq, bk, bv);
    split_qk_kernel<<<dim3(ROWS * 128 / 256, 2), 256>>>();
    hash_tc<<<dim3(256, 2), 256, TC_SMEM2>>>(lshW, lshb);
    hash_fixup<<<64, 256>>>(query, key, Wq, Wk, bq, bk, lshW, lshb);
    bucketize_kernel<<<dim3(32, 2), 256>>>();
    attn_bucket_kernel<<<dim3(256, 32), 256>>>();

    split_att_kernel<<<ROWS * 128 / 256, 256>>>();
    gemm_tc_out<<<dim3(EMB / 128, ROWS / 128), 256, TC_SMEM2>>>(out, bo);
}